// round 13
// baseline (speedup 1.0000x reference)
#include <cuda_runtime.h>
#include <cuda_bf16.h>
#include <cstdint>

// ----------------------------------------------------------------------------
// Problem constants
// ----------------------------------------------------------------------------
#define BATCH     64
#define L_SEQ     256
#define IN_IMG    512
#define IN_PC     256
#define COMB      770
#define DIM       128
#define D_MODEL   1282
#define D_INNER   2564
#define D_STATE   16
#define D_CONV    4
#define DT_RANK   81
#define XPROJ_N   113
#define XPROJ_LD  116
#define M_TOTAL   (BATCH * L_SEQ)      // 16384

#define POOL5_OFF   0
#define POOL9_OFF   1600
#define POOL13_OFF  6784
#define POOL_ROWS   17600

// padded weight dims (rows mult 128, K mult 32)
#define W1_ROWS  5248
#define W1_K     1312
#define W2_ROWS  1408
#define W2_K     2592
#define WX_ROWS  128
#define WX_K     2592
#define WD_ROWS  2688
#define WD_K     96
#define WC_ROWS  512
#define WC_K     800

// ----------------------------------------------------------------------------
// Device scratch (static, ~1.2 GB)
// ----------------------------------------------------------------------------
__device__ __align__(16) float g_seq   [(size_t)M_TOTAL * D_MODEL];
__device__ __align__(16) float g_comb  [(size_t)BATCH * COMB * L_SEQ];
__device__ __align__(16) float g_xz    [(size_t)M_TOTAL * 2 * D_INNER];
__device__ __align__(16) float g_dbl   [(size_t)M_TOTAL * XPROJ_LD];
__device__ __align__(16) float g_dt    [(size_t)M_TOTAL * D_INNER];
__device__ __align__(16) float g_p0    [(size_t)M_TOTAL * DIM];
__device__ __align__(16) float g_y0    [BATCH * DIM];
__device__ __align__(16) float g_pooled[(size_t)POOL_ROWS * COMB];
__device__ __align__(16) float g_ys    [(size_t)POOL_ROWS * DIM];
__device__ __align__(16) float g_bninv [4 * DIM];
__device__ __align__(16) float g_bnbias[4 * DIM];

// pre-split bf16 weights (hi/lo), zero-padded rows & K
__device__ __align__(256) __nv_bfloat16 g_w1h[(size_t)W1_ROWS * W1_K];
__device__ __align__(256) __nv_bfloat16 g_w1l[(size_t)W1_ROWS * W1_K];
__device__ __align__(256) __nv_bfloat16 g_w2h[(size_t)W2_ROWS * W2_K];
__device__ __align__(256) __nv_bfloat16 g_w2l[(size_t)W2_ROWS * W2_K];
__device__ __align__(256) __nv_bfloat16 g_wxh[(size_t)WX_ROWS * WX_K];
__device__ __align__(256) __nv_bfloat16 g_wxl[(size_t)WX_ROWS * WX_K];
__device__ __align__(256) __nv_bfloat16 g_wdh[(size_t)WD_ROWS * WD_K];
__device__ __align__(256) __nv_bfloat16 g_wdl[(size_t)WD_ROWS * WD_K];
__device__ __align__(256) __nv_bfloat16 g_wch[(size_t)WC_ROWS * WC_K];
__device__ __align__(256) __nv_bfloat16 g_wcl[(size_t)WC_ROWS * WC_K];

// pre-split bf16 activations
__device__ __align__(256) __nv_bfloat16 g_ah [(size_t)M_TOTAL * W1_K];
__device__ __align__(256) __nv_bfloat16 g_al [(size_t)M_TOTAL * W1_K];
__device__ __align__(256) __nv_bfloat16 g_uah[(size_t)M_TOTAL * WX_K];
__device__ __align__(256) __nv_bfloat16 g_ual[(size_t)M_TOTAL * WX_K];
__device__ __align__(256) __nv_bfloat16 g_dah[(size_t)M_TOTAL * WD_K];
__device__ __align__(256) __nv_bfloat16 g_dal[(size_t)M_TOTAL * WD_K];
__device__ __align__(256) __nv_bfloat16 g_yh [(size_t)M_TOTAL * W2_K];
__device__ __align__(256) __nv_bfloat16 g_yl [(size_t)M_TOTAL * W2_K];

// ----------------------------------------------------------------------------
// PTX helpers
// ----------------------------------------------------------------------------
__device__ __forceinline__ uint32_t smem_to_u32(const void* p) {
    uint32_t a;
    asm("{ .reg .u64 t; cvta.to.shared.u64 t, %1; cvt.u32.u64 %0, t; }"
        : "=r"(a) : "l"(p));
    return a;
}
#define CP16(smem_u32, gptr) \
    asm volatile("cp.async.cg.shared.global [%0], [%1], 16;" \
                 :: "r"(smem_u32), "l"(gptr))
#define CP_COMMIT() asm volatile("cp.async.commit_group;")
#define CP_WAIT(n)  asm volatile("cp.async.wait_group %0;" :: "n"(n))

__device__ __forceinline__ void ldsm4(uint32_t* f, uint32_t addr) {
    asm volatile("ldmatrix.sync.aligned.m8n8.x4.shared.b16 {%0,%1,%2,%3}, [%4];"
                 : "=r"(f[0]), "=r"(f[1]), "=r"(f[2]), "=r"(f[3]) : "r"(addr));
}
__device__ __forceinline__ void mma16816(float* d, const uint32_t* a,
                                         uint32_t b0, uint32_t b1) {
    asm volatile(
        "mma.sync.aligned.m16n8k16.row.col.f32.bf16.bf16.f32 "
        "{%0,%1,%2,%3}, {%4,%5,%6,%7}, {%8,%9}, {%0,%1,%2,%3};"
        : "+f"(d[0]), "+f"(d[1]), "+f"(d[2]), "+f"(d[3])
        : "r"(a[0]), "r"(a[1]), "r"(a[2]), "r"(a[3]), "r"(b0), "r"(b1));
}
__device__ __forceinline__ void split1(float v, __nv_bfloat16& h, __nv_bfloat16& l) {
    h = __float2bfloat16(v);
    l = __float2bfloat16(v - __bfloat162float(h));
}
__device__ __forceinline__ void cvt_hilo(const float* v, uint4& hi, uint4& lo) {
    uint32_t h[4], l[4];
    #pragma unroll
    for (int i = 0; i < 4; i++) {
        __nv_bfloat16 h0, l0, h1, l1;
        split1(v[2*i], h0, l0);
        split1(v[2*i+1], h1, l1);
        h[i] = (uint32_t)__bfloat16_as_ushort(h0) | ((uint32_t)__bfloat16_as_ushort(h1) << 16);
        l[i] = (uint32_t)__bfloat16_as_ushort(l0) | ((uint32_t)__bfloat16_as_ushort(l1) << 16);
    }
    hi = make_uint4(h[0], h[1], h[2], h[3]);
    lo = make_uint4(l[0], l[1], l[2], l[3]);
}
__device__ __forceinline__ void load_unit(const float* p, bool rowok, int krem,
                                          bool al8, float* v) {
    if (rowok && al8 && krem >= 8) {
        const float2* q = (const float2*)p;
        float2 a = q[0], b = q[1], c = q[2], d = q[3];
        v[0] = a.x; v[1] = a.y; v[2] = b.x; v[3] = b.y;
        v[4] = c.x; v[5] = c.y; v[6] = d.x; v[7] = d.y;
    } else {
        #pragma unroll
        for (int i = 0; i < 8; i++)
            v[i] = (rowok && i < krem) ? p[i] : 0.f;
    }
}

// ----------------------------------------------------------------------------
// fp32 -> bf16 hi/lo split with zero padding; src leading dim srcld
// ----------------------------------------------------------------------------
__global__ void split_kernel(const float* __restrict__ src, int srcld,
                             int R, int K,
                             __nv_bfloat16* __restrict__ hi,
                             __nv_bfloat16* __restrict__ lo,
                             int Rpad, int Kpad) {
    size_t idx = (size_t)blockIdx.x * 256 + threadIdx.x;
    if (idx >= (size_t)Rpad * Kpad) return;
    int k = (int)(idx % Kpad);
    int r = (int)(idx / Kpad);
    float v = (r < R && k < K) ? src[(size_t)r * srcld + k] : 0.f;
    __nv_bfloat16 h, l;
    split1(v, h, l);
    hi[idx] = h;
    lo[idx] = l;
}

// ----------------------------------------------------------------------------
// PIPELINED HMMA bf16x3 GEMM (pre-split A and B, all padded).
// K-chunk 16, 3-stage cp.async pipeline (48KB static smem), 1 sync/chunk.
// Stage planar layout: [AH|AL|BH|BL] x (kh-plane 2KB, row*16B).
// CTA 128x128, 8 warps (2m x 4n), warp 64x32.
// EPI 0: plain fp32   EPI 1: transposed (b,c,l)   EPI 3: softplus(v+eb[n])
// ----------------------------------------------------------------------------
#define PSTG 16384
#define PO_AH 0
#define PO_AL 4096
#define PO_BH 8192
#define PO_BL 12288

template <int EPI>
__global__ __launch_bounds__(256)
void mma_pipe_kernel(const __nv_bfloat16* __restrict__ Ah,
                     const __nv_bfloat16* __restrict__ Al, int lda,
                     const __nv_bfloat16* __restrict__ Bh,
                     const __nv_bfloat16* __restrict__ Bl, int ldb,
                     float* __restrict__ C, int ldc,
                     int M, int N, int Kp,
                     const float* __restrict__ eb) {
    __shared__ __align__(16) unsigned char smem_buf[49152];
    const uint32_t sbase = smem_to_u32(smem_buf);
    const int tid = threadIdx.x;
    const int lane = tid & 31, wid = tid >> 5;
    const int wm = wid >> 2, wn = wid & 3;
    const int bm = blockIdx.y * 128, bn = blockIdx.x * 128;
    const int nchunks = Kp / 16;

    // per-thread cp.async mapping: 256 units of 16B per matrix per chunk
    const int cr = tid >> 1, ckh = tid & 1;
    const uint32_t csoff = (uint32_t)(ckh * 2048 + cr * 16);
    const size_t gA = (size_t)(bm + cr) * lda + ckh * 8;
    const size_t gB = (size_t)(bn + cr) * ldb + ckh * 8;

#define PIPE_ISSUE(ch_) do {                                            \
    uint32_t st_ = sbase + ((ch_) % 3) * PSTG + csoff;                  \
    size_t ko_ = (size_t)(ch_) * 16;                                    \
    CP16(st_ + PO_AH, Ah + gA + ko_);                                   \
    CP16(st_ + PO_AL, Al + gA + ko_);                                   \
    CP16(st_ + PO_BH, Bh + gB + ko_);                                   \
    CP16(st_ + PO_BL, Bl + gB + ko_);                                   \
} while (0)

    float acc[4][4][4];
    #pragma unroll
    for (int i = 0; i < 4; i++)
        #pragma unroll
        for (int j = 0; j < 4; j++)
            #pragma unroll
            for (int q = 0; q < 4; q++) acc[i][j][q] = 0.f;

    const int lrow = lane & 15;
    const int lkh  = lane >> 4;

    PIPE_ISSUE(0); CP_COMMIT();
    if (nchunks > 1) PIPE_ISSUE(1);
    CP_COMMIT();

    for (int ch = 0; ch < nchunks; ch++) {
        CP_WAIT(1);
        __syncthreads();
        if (ch + 2 < nchunks) PIPE_ISSUE(ch + 2);
        CP_COMMIT();

        const uint32_t st = sbase + (ch % 3) * PSTG;
        uint32_t ahf[4][4], alf[4][4];
        #pragma unroll
        for (int mi = 0; mi < 4; mi++) {
            uint32_t off = (uint32_t)(lkh * 2048 + (wm * 64 + mi * 16 + lrow) * 16);
            ldsm4(ahf[mi], st + PO_AH + off);
            ldsm4(alf[mi], st + PO_AL + off);
        }
        #pragma unroll
        for (int ni = 0; ni < 2; ni++) {
            uint32_t off = (uint32_t)(lkh * 2048 + (wn * 32 + ni * 16 + lrow) * 16);
            uint32_t bh[4], bl[4];
            ldsm4(bh, st + PO_BH + off);
            ldsm4(bl, st + PO_BL + off);
            #pragma unroll
            for (int mi = 0; mi < 4; mi++) {
                mma16816(acc[mi][ni * 2 + 0], ahf[mi], bh[0], bh[2]);
                mma16816(acc[mi][ni * 2 + 0], ahf[mi], bl[0], bl[2]);
                mma16816(acc[mi][ni * 2 + 0], alf[mi], bh[0], bh[2]);
                mma16816(acc[mi][ni * 2 + 1], ahf[mi], bh[1], bh[3]);
                mma16816(acc[mi][ni * 2 + 1], ahf[mi], bl[1], bl[3]);
                mma16816(acc[mi][ni * 2 + 1], alf[mi], bh[1], bh[3]);
            }
        }
    }
#undef PIPE_ISSUE

    // ---- epilogue (reuses stage smem; two passes) ----
    const int m0 = bm + wm * 64, n0 = bn + wn * 32;
    const int tr = lane >> 2, tc2 = (lane & 3) * 2;
    #pragma unroll
    for (int pass = 0; pass < 2; pass++) {
        __syncthreads();
        if (wm == pass) {
            float* tp = (float*)(smem_buf + (size_t)wn * 8448);
            #pragma unroll
            for (int mi = 0; mi < 4; mi++)
                #pragma unroll
                for (int nj = 0; nj < 4; nj++) {
                    int r0 = mi * 16 + tr, c0 = nj * 8 + tc2;
                    tp[r0 * 33 + c0]           = acc[mi][nj][0];
                    tp[r0 * 33 + c0 + 1]       = acc[mi][nj][1];
                    tp[(r0 + 8) * 33 + c0]     = acc[mi][nj][2];
                    tp[(r0 + 8) * 33 + c0 + 1] = acc[mi][nj][3];
                }
            __syncwarp();
            if (EPI == 0) {
                int gn = n0 + lane;
                if (gn < N)
                    for (int r = 0; r < 64; r++) {
                        int gm = m0 + r;
                        if (gm < M) C[(size_t)gm * ldc + gn] = tp[r * 33 + lane];
                    }
            } else if (EPI == 3) {
                int gn = n0 + lane;
                if (gn < N) {
                    float bias = eb[gn];
                    for (int r = 0; r < 64; r++) {
                        int gm = m0 + r;
                        if (gm >= M) break;
                        float v = tp[r * 33 + lane] + bias;
                        v = (v > 20.f) ? v : log1pf(expf(v));
                        C[(size_t)gm * ldc + gn] = v;
                    }
                }
            } else {  // EPI 1
                for (int c = 0; c < 32; c++) {
                    int gn = n0 + c;
                    if (gn >= N) break;
                    int m = m0 + lane;
                    int b = m >> 8, l = m & 255;
                    C[((size_t)(b * D_MODEL + gn)) * L_SEQ + l] = tp[lane * 33 + c];
                    m = m0 + 32 + lane;
                    b = m >> 8; l = m & 255;
                    C[((size_t)(b * D_MODEL + gn)) * L_SEQ + l] = tp[(lane + 32) * 33 + c];
                }
            }
        }
    }
}

// ----------------------------------------------------------------------------
// Non-pipelined GEMM for fp32-A cases (conv branches): BN+ReLU6 epilogue
// ----------------------------------------------------------------------------
#define SOFF_AH 0
#define SOFF_AL 8192
#define SOFF_BH 16384
#define SOFF_BL 24576

__global__ __launch_bounds__(256)
void mma_gemm_bn_kernel(const float* __restrict__ A, int lda,
                        const __nv_bfloat16* __restrict__ Bh,
                        const __nv_bfloat16* __restrict__ Bl, int ldb,
                        float* __restrict__ C, int ldc,
                        int M, int N, int K, int Kp,
                        const float* __restrict__ ea, const float* __restrict__ eb) {
    __shared__ __align__(16) unsigned char smem_buf[34048];
    const uint32_t sbase = smem_to_u32(smem_buf);
    const int tid = threadIdx.x;
    const int lane = tid & 31, wid = tid >> 5;
    const int wm = wid >> 2, wn = wid & 3;
    const int bm = blockIdx.y * 128, bn = blockIdx.x * 128;
    const int nchunks = Kp / 32;
    const bool alA = ((lda & 1) == 0);

    float acc[4][4][4];
    #pragma unroll
    for (int i = 0; i < 4; i++)
        #pragma unroll
        for (int j = 0; j < 4; j++)
            #pragma unroll
            for (int q = 0; q < 4; q++) acc[i][j][q] = 0.f;

    const int lrow = lane & 15;
    const int lkh  = lane >> 4;

    for (int ch = 0; ch < nchunks; ch++) {
        const int k0 = ch * 32;
        #pragma unroll
        for (int uu = 0; uu < 2; uu++) {
            int u = tid + uu * 256;
            int r = u >> 2, cu = u & 3;
            uint32_t soff = (uint32_t)(r * 64 + ((cu ^ ((r >> 1) & 3)) << 4));
            int gk = k0 + cu * 8;
            float va[8];
            load_unit(A + (size_t)(bm + r) * lda + gk, (bm + r) < M, K - gk, alA, va);
            uint4 hi, lo;
            cvt_hilo(va, hi, lo);
            *(uint4*)(smem_buf + SOFF_AH + soff) = hi;
            *(uint4*)(smem_buf + SOFF_AL + soff) = lo;
            size_t gob = (size_t)(bn + r) * ldb + gk;
            *(uint4*)(smem_buf + SOFF_BH + soff) = *(const uint4*)(Bh + gob);
            *(uint4*)(smem_buf + SOFF_BL + soff) = *(const uint4*)(Bl + gob);
        }
        __syncthreads();
        #pragma unroll
        for (int k16 = 0; k16 < 2; k16++) {
            const int cbase = k16 * 2 + lkh;
            uint32_t ahf[4][4], alf[4][4];
            #pragma unroll
            for (int mi = 0; mi < 4; mi++) {
                int r = wm * 64 + mi * 16 + lrow;
                uint32_t off = (uint32_t)(r * 64 + ((cbase ^ ((r >> 1) & 3)) << 4));
                ldsm4(ahf[mi], sbase + SOFF_AH + off);
                ldsm4(alf[mi], sbase + SOFF_AL + off);
            }
            #pragma unroll
            for (int ni = 0; ni < 2; ni++) {
                int r = wn * 32 + ni * 16 + lrow;
                uint32_t off = (uint32_t)(r * 64 + ((cbase ^ ((r >> 1) & 3)) << 4));
                uint32_t bh[4], bl[4];
                ldsm4(bh, sbase + SOFF_BH + off);
                ldsm4(bl, sbase + SOFF_BL + off);
                #pragma unroll
                for (int mi = 0; mi < 4; mi++) {
                    mma16816(acc[mi][ni * 2 + 0], ahf[mi], bh[0], bh[2]);
                    mma16816(acc[mi][ni * 2 + 0], ahf[mi], bl[0], bl[2]);
                    mma16816(acc[mi][ni * 2 + 0], alf[mi], bh[0], bh[2]);
                    mma16816(acc[mi][ni * 2 + 1], ahf[mi], bh[1], bh[3]);
                    mma16816(acc[mi][ni * 2 + 1], ahf[mi], bl[1], bl[3]);
                    mma16816(acc[mi][ni * 2 + 1], alf[mi], bh[1], bh[3]);
                }
            }
        }
        __syncthreads();
    }

    const int m0 = bm + wm * 64, n0 = bn + wn * 32;
    const int tr = lane >> 2, tc2 = (lane & 3) * 2;
    #pragma unroll
    for (int pass = 0; pass < 2; pass++) {
        __syncthreads();
        if (wm == pass) {
            float* tp = (float*)(smem_buf + (size_t)wn * 8448);
            #pragma unroll
            for (int mi = 0; mi < 4; mi++)
                #pragma unroll
                for (int nj = 0; nj < 4; nj++) {
                    int r0 = mi * 16 + tr, c0 = nj * 8 + tc2;
                    tp[r0 * 33 + c0]           = acc[mi][nj][0];
                    tp[r0 * 33 + c0 + 1]       = acc[mi][nj][1];
                    tp[(r0 + 8) * 33 + c0]     = acc[mi][nj][2];
                    tp[(r0 + 8) * 33 + c0 + 1] = acc[mi][nj][3];
                }
            __syncwarp();
            int gn = n0 + lane;
            if (gn < N) {
                float sa = ea[gn], sb = eb[gn];
                for (int r = 0; r < 64; r++) {
                    int gm = m0 + r;
                    if (gm >= M) break;
                    float v = tp[r * 33 + lane] * sa + sb;
                    v = fminf(fmaxf(v, 0.f), 6.f);
                    C[(size_t)gm * ldc + gn] = v;
                }
            }
        }
    }
}

// ----------------------------------------------------------------------------
__global__ void prep_bn_kernel(const float* __restrict__ gamma,
                               const float* __restrict__ beta,
                               const float* __restrict__ mean,
                               const float* __restrict__ var) {
    int i = blockIdx.x * 256 + threadIdx.x;
    if (i < 4 * DIM) {
        float iv = rsqrtf(var[i] + 1e-5f) * gamma[i];
        g_bninv[i]  = iv;
        g_bnbias[i] = beta[i] - mean[i] * iv;
    }
}

// ----------------------------------------------------------------------------
__global__ void build_comb_kernel(const float* __restrict__ x,
                                  const float* __restrict__ pc) {
    size_t idx = (size_t)blockIdx.x * 256 + threadIdx.x;
    if (idx >= (size_t)BATCH * COMB * L_SEQ) return;
    int l = (int)(idx % L_SEQ);
    int c = (int)((idx / L_SEQ) % COMB);
    int b = (int)(idx / ((size_t)L_SEQ * COMB));
    float v;
    if (c < IN_IMG) {
        v = x[((size_t)(b * IN_IMG + c)) * L_SEQ + l];
    } else if (c == IN_IMG) {
        int w = l & 15;
        v = -0.3f + 0.6f * (float)w / 15.0f;
    } else if (c == IN_IMG + 1) {
        int h = l >> 4;
        v = -0.3f + 0.6f * (float)h / 15.0f;
    } else {
        v = pc[b * IN_PC + (c - IN_IMG - 2)];
    }
    g_comb[((size_t)(b * COMB + c)) * L_SEQ + l] = v;
    g_seq[((size_t)(b * L_SEQ + l)) * D_MODEL + c] = v;
}

// ----------------------------------------------------------------------------
__global__ void pool_avg_kernel() {
    __shared__ float s[32][257];
    int b  = blockIdx.y;
    int c0 = blockIdx.x * 32;
    int tid = threadIdx.x;
    for (int i = tid; i < 32 * 256; i += 256) {
        int cl = i >> 8, l = i & 255;
        int c = c0 + cl;
        s[cl][l] = (c < COMB) ? g_comb[((size_t)(b * COMB + c)) * L_SEQ + l] : 0.f;
    }
    __syncthreads();
    for (int oidx = tid; oidx < 275 * 32; oidx += 256) {
        int cl = oidx & 31;
        int q  = oidx >> 5;
        int sdim, qb, base;
        if (q < 25)       { sdim = 5;  qb = q;       base = POOL5_OFF;  }
        else if (q < 106) { sdim = 9;  qb = q - 25;  base = POOL9_OFF;  }
        else              { sdim = 13; qb = q - 106; base = POOL13_OFF; }
        int o = qb / sdim, p = qb % sdim;
        int h0 = (o * 16) / sdim, h1 = ((o + 1) * 16 + sdim - 1) / sdim;
        int w0 = (p * 16) / sdim, w1 = ((p + 1) * 16 + sdim - 1) / sdim;
        float sum = 0.f;
        for (int h = h0; h < h1; h++)
            for (int w = w0; w < w1; w++)
                sum += s[cl][h * 16 + w];
        sum *= 1.0f / (float)((h1 - h0) * (w1 - w0));
        int c = c0 + cl;
        if (c < COMB)
            g_pooled[((size_t)(base + b * sdim * sdim + qb)) * COMB + c] = sum;
    }
}

// ----------------------------------------------------------------------------
__global__ void pool0_mean_kernel() {
    int b = blockIdx.x;
    int d = threadIdx.x;
    float s = 0.f;
    for (int l = 0; l < L_SEQ; l++)
        s += g_p0[((size_t)(b * L_SEQ + l)) * DIM + d];
    g_y0[b * DIM + d] = s * (1.0f / (float)L_SEQ);
}

// ----------------------------------------------------------------------------
__global__ void fill_pool_cols_kernel() {
    int m = blockIdx.x;
    int t = threadIdx.x;
    int b = m >> 8, l = m & 255;
    int h = l >> 4, w = l & 15;
    int si = t >> 7, d = t & 127;
    float v;
    if (si == 0) {
        v = g_y0[b * DIM + d];
    } else {
        int sdim = (si == 1) ? 5 : (si == 2) ? 9 : 13;
        int base = (si == 1) ? POOL5_OFF : (si == 2) ? POOL9_OFF : POOL13_OFF;
        float sh = (h + 0.5f) * (float)sdim / 16.0f - 0.5f;
        sh = fminf(fmaxf(sh, 0.f), (float)sdim - 1.f);
        int h0 = (int)sh;
        int h1 = min(h0 + 1, sdim - 1);
        float fh = sh - (float)h0;
        float sw = (w + 0.5f) * (float)sdim / 16.0f - 0.5f;
        sw = fminf(fmaxf(sw, 0.f), (float)sdim - 1.f);
        int w0 = (int)sw;
        int w1 = min(w0 + 1, sdim - 1);
        float fw = sw - (float)w0;
        const float* Y = g_ys + (size_t)(base + b * sdim * sdim) * DIM;
        float v00 = Y[(size_t)(h0 * sdim + w0) * DIM + d];
        float v01 = Y[(size_t)(h0 * sdim + w1) * DIM + d];
        float v10 = Y[(size_t)(h1 * sdim + w0) * DIM + d];
        float v11 = Y[(size_t)(h1 * sdim + w1) * DIM + d];
        v = (1.f - fh) * ((1.f - fw) * v00 + fw * v01)
          +        fh  * ((1.f - fw) * v10 + fw * v11);
    }
    g_seq[(size_t)m * D_MODEL + COMB + t] = v;
}

// ----------------------------------------------------------------------------
// conv1d + SiLU; writes u as bf16 split (coalesced along d), pads zeroed
// ----------------------------------------------------------------------------
__global__ void conv1d_silu_kernel(const float* __restrict__ w,
                                   const float* __restrict__ bias) {
    int d = blockIdx.x * 256 + threadIdx.x;
    int m = blockIdx.y;
    if (d >= WX_K) return;
    __nv_bfloat16 h, lo;
    if (d < D_INNER) {
        int b = m >> 8, l = m & 255;
        float acc = bias[d];
        #pragma unroll
        for (int k = 0; k < D_CONV; k++) {
            int ls = l + k - (D_CONV - 1);
            if (ls >= 0)
                acc += w[d * D_CONV + k] * g_xz[((size_t)(b * L_SEQ + ls)) * (2 * D_INNER) + d];
        }
        float sg = 1.f / (1.f + __expf(-acc));
        split1(acc * sg, h, lo);
    } else {
        h = __float2bfloat16(0.f);
        lo = h;
    }
    g_uah[(size_t)m * WX_K + d] = h;
    g_ual[(size_t)m * WX_K + d] = lo;
}

// ----------------------------------------------------------------------------
// selective scan; u reconstructed from split; writes y split directly
// ----------------------------------------------------------------------------
__global__ __launch_bounds__(256)
void scan_kernel(const float* __restrict__ A_log, const float* __restrict__ Dp) {
    __shared__ float sB[L_SEQ][D_STATE];
    __shared__ float sC[L_SEQ][D_STATE];
    int b = blockIdx.y;
    int d = blockIdx.x * 256 + threadIdx.x;
    int tid = threadIdx.x;
    for (int i = tid; i < L_SEQ * D_STATE; i += 256) {
        int l = i >> 4, n = i & 15;
        const float* row = g_dbl + (size_t)(b * L_SEQ + l) * XPROJ_LD;
        sB[l][n] = row[DT_RANK + n];
        sC[l][n] = row[DT_RANK + D_STATE + n];
    }
    __syncthreads();
    if (d >= D_INNER) {
        if (d < W2_K) {
            __nv_bfloat16 z16 = __float2bfloat16(0.f);
            for (int l = 0; l < L_SEQ; l++) {
                size_t m = (size_t)(b * L_SEQ + l);
                g_yh[m * W2_K + d] = z16;
                g_yl[m * W2_K + d] = z16;
            }
        }
        return;
    }

    float Ad[D_STATE];
    #pragma unroll
    for (int n = 0; n < D_STATE; n++) Ad[n] = -expf(A_log[d * D_STATE + n]);
    float Dd = Dp[d];
    float hst[D_STATE];
    #pragma unroll
    for (int n = 0; n < D_STATE; n++) hst[n] = 0.f;

    for (int l = 0; l < L_SEQ; l++) {
        size_t m = (size_t)(b * L_SEQ + l);
        float dt = g_dt[m * D_INNER + d];
        float u  = __bfloat162float(g_uah[m * WX_K + d])
                 + __bfloat162float(g_ual[m * WX_K + d]);
        float z  = g_xz[m * (2 * D_INNER) + D_INNER + d];
        float dtu = dt * u;
        float y = 0.f;
        #pragma unroll
        for (int n = 0; n < D_STATE; n++) {
            float dA = __expf(dt * Ad[n]);
            hst[n] = dA * hst[n] + dtu * sB[l][n];
            y = fmaf(hst[n], sC[l][n], y);
        }
        float sig = 1.f / (1.f + __expf(-z));
        float v = (y + u * Dd) * (z * sig);
        __nv_bfloat16 hh, ll;
        split1(v, hh, ll);
        g_yh[m * W2_K + d] = hh;
        g_yl[m * W2_K + d] = ll;
    }
}

// ----------------------------------------------------------------------------
extern "C" void kernel_launch(void* const* d_in, const int* in_sizes, int n_in,
                              void* d_out, int out_size) {
    const float* x          = (const float*)d_in[0];
    const float* pc_emb     = (const float*)d_in[1];
    const float* conv_w     = (const float*)d_in[2];
    const float* bn_gamma   = (const float*)d_in[3];
    const float* bn_beta    = (const float*)d_in[4];
    const float* bn_mean    = (const float*)d_in[5];
    const float* bn_var     = (const float*)d_in[6];
    const float* in_proj_w  = (const float*)d_in[7];
    const float* conv1d_w   = (const float*)d_in[8];
    const float* conv1d_b   = (const float*)d_in[9];
    const float* x_proj_w   = (const float*)d_in[10];
    const float* dt_proj_w  = (const float*)d_in[11];
    const float* dt_proj_b  = (const float*)d_in[12];
    const float* A_log      = (const float*)d_in[13];
    const float* Dp         = (const float*)d_in[14];
    const float* out_proj_w = (const float*)d_in[15];
    float* out = (float*)d_out;

    float *p_seq, *p_xz, *p_dbl, *p_dt, *p_p0, *p_pooled, *p_ys, *p_bninv, *p_bnbias;
    __nv_bfloat16 *p_w1h, *p_w1l, *p_w2h, *p_w2l, *p_wxh, *p_wxl, *p_wdh, *p_wdl, *p_wch, *p_wcl;
    __nv_bfloat16 *p_ah, *p_al, *p_uah, *p_ual, *p_dah, *p_dal, *p_yh, *p_yl;
    cudaGetSymbolAddress((void**)&p_seq,    g_seq);
    cudaGetSymbolAddress((void**)&p_xz,     g_xz);
    cudaGetSymbolAddress((void**)&p_dbl,    g_dbl);
    cudaGetSymbolAddress((void**)&p_dt,     g_dt);
    cudaGetSymbolAddress((void**)&p_p0,     g_p0);
    cudaGetSymbolAddress((void**)&p_pooled, g_pooled);
    cudaGetSymbolAddress((void**)&p_ys,     g_ys);
    cudaGetSymbolAddress((void**)&p_bninv,  g_bninv);
    cudaGetSymbolAddress((void**)&p_bnbias, g_bnbias);
    cudaGetSymbolAddress((void**)&p_w1h, g_w1h);  cudaGetSymbolAddress((void**)&p_w1l, g_w1l);
    cudaGetSymbolAddress((void**)&p_w2h, g_w2h);  cudaGetSymbolAddress((void**)&p_w2l, g_w2l);
    cudaGetSymbolAddress((void**)&p_wxh, g_wxh);  cudaGetSymbolAddress((void**)&p_wxl, g_wxl);
    cudaGetSymbolAddress((void**)&p_wdh, g_wdh);  cudaGetSymbolAddress((void**)&p_wdl, g_wdl);
    cudaGetSymbolAddress((void**)&p_wch, g_wch);  cudaGetSymbolAddress((void**)&p_wcl, g_wcl);
    cudaGetSymbolAddress((void**)&p_ah,  g_ah);   cudaGetSymbolAddress((void**)&p_al,  g_al);
    cudaGetSymbolAddress((void**)&p_uah, g_uah);  cudaGetSymbolAddress((void**)&p_ual, g_ual);
    cudaGetSymbolAddress((void**)&p_dah, g_dah);  cudaGetSymbolAddress((void**)&p_dal, g_dal);
    cudaGetSymbolAddress((void**)&p_yh,  g_yh);   cudaGetSymbolAddress((void**)&p_yl,  g_yl);

    // 1) BN fold + weight pre-splits
    prep_bn_kernel<<<2, 256>>>(bn_gamma, bn_beta, bn_mean, bn_var);
    {
        size_t n;
        n = (size_t)WC_ROWS * WC_K;
        split_kernel<<<(unsigned)((n + 255) / 256), 256>>>(conv_w, COMB, 512, COMB, p_wch, p_wcl, WC_ROWS, WC_K);
        n = (size_t)W1_ROWS * W1_K;
        split_kernel<<<(unsigned)((n + 255) / 256), 256>>>(in_proj_w, D_MODEL, 2 * D_INNER, D_MODEL, p_w1h, p_w1l, W1_ROWS, W1_K);
        n = (size_t)WX_ROWS * WX_K;
        split_kernel<<<(unsigned)((n + 255) / 256), 256>>>(x_proj_w, D_INNER, XPROJ_N, D_INNER, p_wxh, p_wxl, WX_ROWS, WX_K);
        n = (size_t)WD_ROWS * WD_K;
        split_kernel<<<(unsigned)((n + 255) / 256), 256>>>(dt_proj_w, DT_RANK, D_INNER, DT_RANK, p_wdh, p_wdl, WD_ROWS, WD_K);
        n = (size_t)W2_ROWS * W2_K;
        split_kernel<<<(unsigned)((n + 255) / 256), 256>>>(out_proj_w, D_INNER, D_MODEL, D_INNER, p_w2h, p_w2l, W2_ROWS, W2_K);
    }

    // 2) build comb
    {
        size_t total = (size_t)BATCH * COMB * L_SEQ;
        build_comb_kernel<<<(unsigned)((total + 255) / 256), 256>>>(x, pc_emb);
    }

    // 3) adaptive pools
    pool_avg_kernel<<<dim3(25, BATCH), 256>>>();

    // 4) conv0 full-res (fp32-A kernel)
    mma_gemm_bn_kernel<<<dim3(1, M_TOTAL / 128), 256>>>(
        p_seq, D_MODEL, p_wch, p_wcl, WC_K, p_p0, DIM,
        M_TOTAL, DIM, COMB, WC_K, p_bninv, p_bnbias);

    // 5) pool0 mean
    pool0_mean_kernel<<<BATCH, DIM>>>();

    // 6) pooled-branch convs
    {
        const int sM[3]   = {1600, 5184, 10816};
        const int sOff[3] = {POOL5_OFF, POOL9_OFF, POOL13_OFF};
        for (int i = 0; i < 3; i++) {
            int pool = i + 1;
            mma_gemm_bn_kernel<<<dim3(1, (sM[i] + 127) / 128), 256>>>(
                p_pooled + (size_t)sOff[i] * COMB, COMB,
                p_wch + (size_t)pool * DIM * WC_K, p_wcl + (size_t)pool * DIM * WC_K, WC_K,
                p_ys + (size_t)sOff[i] * DIM, DIM,
                sM[i], DIM, COMB, WC_K,
                p_bninv + pool * DIM, p_bnbias + pool * DIM);
        }
    }

    // 7) fill pool cols, split seq -> bf16 hi/lo
    fill_pool_cols_kernel<<<M_TOTAL, 512>>>();
    {
        size_t n = (size_t)M_TOTAL * W1_K;
        split_kernel<<<(unsigned)((n + 255) / 256), 256>>>(
            p_seq, D_MODEL, M_TOTAL, D_MODEL, p_ah, p_al, M_TOTAL, W1_K);
    }

    // 8) in_proj (pipelined) -> g_xz
    mma_pipe_kernel<0><<<dim3(W1_ROWS / 128, M_TOTAL / 128), 256>>>(
        p_ah, p_al, W1_K, p_w1h, p_w1l, W1_K, p_xz, 2 * D_INNER,
        M_TOTAL, 2 * D_INNER, W1_K, nullptr);

    // 9) conv1d + SiLU (writes u split)
    conv1d_silu_kernel<<<dim3((WX_K + 255) / 256, M_TOTAL), 256>>>(conv1d_w, conv1d_b);

    // 10) x_proj (pipelined) -> g_dbl
    mma_pipe_kernel<0><<<dim3(1, M_TOTAL / 128), 256>>>(
        p_uah, p_ual, WX_K, p_wxh, p_wxl, WX_K, p_dbl, XPROJ_LD,
        M_TOTAL, XPROJ_N, WX_K, nullptr);

    // 10b) split dtA (cols 0..80 of g_dbl)
    {
        size_t n = (size_t)M_TOTAL * WD_K;
        split_kernel<<<(unsigned)((n + 255) / 256), 256>>>(
            p_dbl, XPROJ_LD, M_TOTAL, DT_RANK, p_dah, p_dal, M_TOTAL, WD_K);
    }

    // 11) dt_proj (pipelined, softplus) -> g_dt
    mma_pipe_kernel<3><<<dim3(WD_ROWS / 128, M_TOTAL / 128), 256>>>(
        p_dah, p_dal, WD_K, p_wdh, p_wdl, WD_K, p_dt, D_INNER,
        M_TOTAL, D_INNER, WD_K, dt_proj_b);

    // 12) selective scan (writes y split directly)
    scan_kernel<<<dim3((W2_K + 255) / 256, BATCH), 256>>>(A_log, Dp);

    // 13) out_proj (pipelined, fused transpose) -> out
    mma_pipe_kernel<1><<<dim3(W2_ROWS / 128, M_TOTAL / 128), 256>>>(
        p_yh, p_yl, W2_K, p_w2h, p_w2l, W2_K, out, 0,
        M_TOTAL, D_MODEL, W2_K, nullptr);
}

// round 15
// speedup vs baseline: 1.1987x; 1.1987x over previous
#include <cuda_runtime.h>
#include <cuda_bf16.h>
#include <cstdint>

// ----------------------------------------------------------------------------
// Problem constants
// ----------------------------------------------------------------------------
#define BATCH     64
#define L_SEQ     256
#define IN_IMG    512
#define IN_PC     256
#define COMB      770
#define DIM       128
#define D_MODEL   1282
#define D_INNER   2564
#define D_STATE   16
#define D_CONV    4
#define DT_RANK   81
#define XPROJ_N   113
#define XPROJ_LD  116
#define M_TOTAL   (BATCH * L_SEQ)      // 16384

#define POOL5_OFF   0
#define POOL9_OFF   1600
#define POOL13_OFF  6784
#define POOL_ROWS   17600

// padded weight dims (rows mult 128, K mult 32)
#define W1_ROWS  5248
#define W1_K     1312
#define W2_ROWS  1408
#define W2_K     2592
#define WX_ROWS  128
#define WX_K     2592
#define WD_ROWS  2688
#define WD_K     96
#define WC_ROWS  512
#define WC_K     800

// ----------------------------------------------------------------------------
// Device scratch (static)
// ----------------------------------------------------------------------------
__device__ __align__(16) float g_seq   [(size_t)M_TOTAL * D_MODEL];
__device__ __align__(16) float g_comb  [(size_t)BATCH * COMB * L_SEQ];
__device__ __align__(16) float g_xz    [(size_t)M_TOTAL * 2 * D_INNER];
__device__ __align__(16) float g_dbl   [(size_t)M_TOTAL * XPROJ_LD];
__device__ __align__(16) float g_dt    [(size_t)M_TOTAL * D_INNER];
__device__ __align__(16) float g_p0    [(size_t)M_TOTAL * DIM];
__device__ __align__(16) float g_y0    [BATCH * DIM];
__device__ __align__(16) float g_pooled[(size_t)POOL_ROWS * COMB];
__device__ __align__(16) float g_ys    [(size_t)POOL_ROWS * DIM];
__device__ __align__(16) float g_bninv [4 * DIM];
__device__ __align__(16) float g_bnbias[4 * DIM];

// pre-split bf16 weights (hi/lo), zero-padded rows & K
__device__ __align__(256) __nv_bfloat16 g_w1h[(size_t)W1_ROWS * W1_K];
__device__ __align__(256) __nv_bfloat16 g_w1l[(size_t)W1_ROWS * W1_K];
__device__ __align__(256) __nv_bfloat16 g_w2h[(size_t)W2_ROWS * W2_K];
__device__ __align__(256) __nv_bfloat16 g_w2l[(size_t)W2_ROWS * W2_K];
__device__ __align__(256) __nv_bfloat16 g_wxh[(size_t)WX_ROWS * WX_K];
__device__ __align__(256) __nv_bfloat16 g_wxl[(size_t)WX_ROWS * WX_K];
__device__ __align__(256) __nv_bfloat16 g_wdh[(size_t)WD_ROWS * WD_K];
__device__ __align__(256) __nv_bfloat16 g_wdl[(size_t)WD_ROWS * WD_K];
__device__ __align__(256) __nv_bfloat16 g_wch[(size_t)WC_ROWS * WC_K];
__device__ __align__(256) __nv_bfloat16 g_wcl[(size_t)WC_ROWS * WC_K];

// pre-split bf16 activations
__device__ __align__(256) __nv_bfloat16 g_ah [(size_t)M_TOTAL * W1_K];
__device__ __align__(256) __nv_bfloat16 g_al [(size_t)M_TOTAL * W1_K];
__device__ __align__(256) __nv_bfloat16 g_uah[(size_t)M_TOTAL * WX_K];
__device__ __align__(256) __nv_bfloat16 g_ual[(size_t)M_TOTAL * WX_K];
__device__ __align__(256) __nv_bfloat16 g_dah[(size_t)M_TOTAL * WD_K];
__device__ __align__(256) __nv_bfloat16 g_dal[(size_t)M_TOTAL * WD_K];
__device__ __align__(256) __nv_bfloat16 g_yh [(size_t)M_TOTAL * W2_K];
__device__ __align__(256) __nv_bfloat16 g_yl [(size_t)M_TOTAL * W2_K];

// ----------------------------------------------------------------------------
// PTX helpers
// ----------------------------------------------------------------------------
__device__ __forceinline__ uint32_t smem_to_u32(const void* p) {
    uint32_t a;
    asm("{ .reg .u64 t; cvta.to.shared.u64 t, %1; cvt.u32.u64 %0, t; }"
        : "=r"(a) : "l"(p));
    return a;
}
__device__ __forceinline__ void ldsm4(uint32_t* f, uint32_t addr) {
    asm volatile("ldmatrix.sync.aligned.m8n8.x4.shared.b16 {%0,%1,%2,%3}, [%4];"
                 : "=r"(f[0]), "=r"(f[1]), "=r"(f[2]), "=r"(f[3]) : "r"(addr));
}
__device__ __forceinline__ void mma16816(float* d, const uint32_t* a,
                                         uint32_t b0, uint32_t b1) {
    asm volatile(
        "mma.sync.aligned.m16n8k16.row.col.f32.bf16.bf16.f32 "
        "{%0,%1,%2,%3}, {%4,%5,%6,%7}, {%8,%9}, {%0,%1,%2,%3};"
        : "+f"(d[0]), "+f"(d[1]), "+f"(d[2]), "+f"(d[3])
        : "r"(a[0]), "r"(a[1]), "r"(a[2]), "r"(a[3]), "r"(b0), "r"(b1));
}
__device__ __forceinline__ void split1(float v, __nv_bfloat16& h, __nv_bfloat16& l) {
    h = __float2bfloat16(v);
    l = __float2bfloat16(v - __bfloat162float(h));
}
__device__ __forceinline__ void cvt_hilo(const float* v, uint4& hi, uint4& lo) {
    uint32_t h[4], l[4];
    #pragma unroll
    for (int i = 0; i < 4; i++) {
        __nv_bfloat16 h0, l0, h1, l1;
        split1(v[2*i], h0, l0);
        split1(v[2*i+1], h1, l1);
        h[i] = (uint32_t)__bfloat16_as_ushort(h0) | ((uint32_t)__bfloat16_as_ushort(h1) << 16);
        l[i] = (uint32_t)__bfloat16_as_ushort(l0) | ((uint32_t)__bfloat16_as_ushort(l1) << 16);
    }
    hi = make_uint4(h[0], h[1], h[2], h[3]);
    lo = make_uint4(l[0], l[1], l[2], l[3]);
}
__device__ __forceinline__ void load_unit(const float* p, bool rowok, int krem,
                                          bool al8, float* v) {
    if (rowok && al8 && krem >= 8) {
        const float2* q = (const float2*)p;
        float2 a = q[0], b = q[1], c = q[2], d = q[3];
        v[0] = a.x; v[1] = a.y; v[2] = b.x; v[3] = b.y;
        v[4] = c.x; v[5] = c.y; v[6] = d.x; v[7] = d.y;
    } else {
        #pragma unroll
        for (int i = 0; i < 8; i++)
            v[i] = (rowok && i < krem) ? p[i] : 0.f;
    }
}

// ----------------------------------------------------------------------------
// fp32 -> bf16 hi/lo split with zero padding; src leading dim srcld
// ----------------------------------------------------------------------------
__global__ void split_kernel(const float* __restrict__ src, int srcld,
                             int R, int K,
                             __nv_bfloat16* __restrict__ hi,
                             __nv_bfloat16* __restrict__ lo,
                             int Rpad, int Kpad) {
    size_t idx = (size_t)blockIdx.x * 256 + threadIdx.x;
    if (idx >= (size_t)Rpad * Kpad) return;
    int k = (int)(idx % Kpad);
    int r = (int)(idx / Kpad);
    float v = (r < R && k < K) ? src[(size_t)r * srcld + k] : 0.f;
    __nv_bfloat16 h, l;
    split1(v, h, l);
    hi[idx] = h;
    lo[idx] = l;
}

// ----------------------------------------------------------------------------
// HMMA bf16x3-split GEMM (R12-proven config).
//   ASP=false: A fp32, in-register split    ASP=true: A pre-split bf16 hi/lo
// B always pre-split bf16 hi/lo, padded.
// CTA 128x128, 8 warps (2m x 4n), warp 64x32, K-chunk 32, single-stage smem.
// EPI 0: plain fp32   EPI 1: transposed (b,c,l)   EPI 3: softplus   EPI 4: BN+ReLU6
// ----------------------------------------------------------------------------
#define SOFF_AH 0
#define SOFF_AL 8192
#define SOFF_BH 16384
#define SOFF_BL 24576

template <int EPI, bool ASP>
__global__ __launch_bounds__(256)
void mma_gemm_kernel(const void* __restrict__ Aah, const void* __restrict__ Aal,
                     int lda,
                     const __nv_bfloat16* __restrict__ Bh,
                     const __nv_bfloat16* __restrict__ Bl, int ldb,
                     float* __restrict__ C, int ldc,
                     int M, int N, int K, int Kp,
                     const float* __restrict__ ea, const float* __restrict__ eb) {
    __shared__ __align__(16) unsigned char smem_buf[34048];
    const uint32_t sbase = smem_to_u32(smem_buf);
    const int tid = threadIdx.x;
    const int lane = tid & 31, wid = tid >> 5;
    const int wm = wid >> 2, wn = wid & 3;
    const int bm = blockIdx.y * 128, bn = blockIdx.x * 128;
    const int nchunks = Kp / 32;
    const bool alA = ((lda & 1) == 0);

    float acc[4][4][4];
    #pragma unroll
    for (int i = 0; i < 4; i++)
        #pragma unroll
        for (int j = 0; j < 4; j++)
            #pragma unroll
            for (int q = 0; q < 4; q++) acc[i][j][q] = 0.f;

    const int lrow = lane & 15;
    const int lkh  = lane >> 4;

    for (int ch = 0; ch < nchunks; ch++) {
        const int k0 = ch * 32;
        #pragma unroll
        for (int uu = 0; uu < 2; uu++) {
            int u = tid + uu * 256;
            int r = u >> 2, cu = u & 3;
            uint32_t soff = (uint32_t)(r * 64 + ((cu ^ ((r >> 1) & 3)) << 4));
            int gk = k0 + cu * 8;
            if (ASP) {
                size_t goa = (size_t)(bm + r) * lda + gk;
                *(uint4*)(smem_buf + SOFF_AH + soff) =
                    *(const uint4*)((const __nv_bfloat16*)Aah + goa);
                *(uint4*)(smem_buf + SOFF_AL + soff) =
                    *(const uint4*)((const __nv_bfloat16*)Aal + goa);
            } else {
                float va[8];
                load_unit((const float*)Aah + (size_t)(bm + r) * lda + gk,
                          (bm + r) < M, K - gk, alA, va);
                uint4 hi, lo;
                cvt_hilo(va, hi, lo);
                *(uint4*)(smem_buf + SOFF_AH + soff) = hi;
                *(uint4*)(smem_buf + SOFF_AL + soff) = lo;
            }
            size_t gob = (size_t)(bn + r) * ldb + gk;
            *(uint4*)(smem_buf + SOFF_BH + soff) = *(const uint4*)(Bh + gob);
            *(uint4*)(smem_buf + SOFF_BL + soff) = *(const uint4*)(Bl + gob);
        }
        __syncthreads();
        #pragma unroll
        for (int k16 = 0; k16 < 2; k16++) {
            const int cbase = k16 * 2 + lkh;
            uint32_t ahf[4][4], alf[4][4], bhf[4][2], blf[4][2];
            #pragma unroll
            for (int mi = 0; mi < 4; mi++) {
                int r = wm * 64 + mi * 16 + lrow;
                uint32_t off = (uint32_t)(r * 64 + ((cbase ^ ((r >> 1) & 3)) << 4));
                ldsm4(ahf[mi], sbase + SOFF_AH + off);
                ldsm4(alf[mi], sbase + SOFF_AL + off);
            }
            #pragma unroll
            for (int ni = 0; ni < 2; ni++) {
                int r = wn * 32 + ni * 16 + lrow;
                uint32_t off = (uint32_t)(r * 64 + ((cbase ^ ((r >> 1) & 3)) << 4));
                uint32_t bt[4];
                ldsm4(bt, sbase + SOFF_BH + off);
                bhf[ni * 2 + 0][0] = bt[0]; bhf[ni * 2 + 0][1] = bt[2];
                bhf[ni * 2 + 1][0] = bt[1]; bhf[ni * 2 + 1][1] = bt[3];
                ldsm4(bt, sbase + SOFF_BL + off);
                blf[ni * 2 + 0][0] = bt[0]; blf[ni * 2 + 0][1] = bt[2];
                blf[ni * 2 + 1][0] = bt[1]; blf[ni * 2 + 1][1] = bt[3];
            }
            #pragma unroll
            for (int mi = 0; mi < 4; mi++)
                #pragma unroll
                for (int nj = 0; nj < 4; nj++) {
                    mma16816(acc[mi][nj], ahf[mi], bhf[nj][0], bhf[nj][1]);
                    mma16816(acc[mi][nj], ahf[mi], blf[nj][0], blf[nj][1]);
                    mma16816(acc[mi][nj], alf[mi], bhf[nj][0], bhf[nj][1]);
                }
        }
        __syncthreads();
    }

    // ---- epilogue ----
    const int m0 = bm + wm * 64, n0 = bn + wn * 32;
    const int tr = lane >> 2, tc2 = (lane & 3) * 2;
    #pragma unroll
    for (int pass = 0; pass < 2; pass++) {
        __syncthreads();
        if (wm == pass) {
            float* tp = (float*)(smem_buf + (size_t)wn * 8448);
            #pragma unroll
            for (int mi = 0; mi < 4; mi++)
                #pragma unroll
                for (int nj = 0; nj < 4; nj++) {
                    int r0 = mi * 16 + tr, c0 = nj * 8 + tc2;
                    tp[r0 * 33 + c0]           = acc[mi][nj][0];
                    tp[r0 * 33 + c0 + 1]       = acc[mi][nj][1];
                    tp[(r0 + 8) * 33 + c0]     = acc[mi][nj][2];
                    tp[(r0 + 8) * 33 + c0 + 1] = acc[mi][nj][3];
                }
            __syncwarp();
            if (EPI == 0) {
                int gn = n0 + lane;
                if (gn < N)
                    for (int r = 0; r < 64; r++) {
                        int gm = m0 + r;
                        if (gm < M) C[(size_t)gm * ldc + gn] = tp[r * 33 + lane];
                    }
            } else if (EPI == 3) {
                int gn = n0 + lane;
                if (gn < N) {
                    float bias = eb[gn];
                    for (int r = 0; r < 64; r++) {
                        int gm = m0 + r;
                        if (gm >= M) break;
                        float v = tp[r * 33 + lane] + bias;
                        v = (v > 20.f) ? v : log1pf(expf(v));
                        C[(size_t)gm * ldc + gn] = v;
                    }
                }
            } else if (EPI == 4) {
                int gn = n0 + lane;
                if (gn < N) {
                    float sa = ea[gn], sb = eb[gn];
                    for (int r = 0; r < 64; r++) {
                        int gm = m0 + r;
                        if (gm >= M) break;
                        float v = tp[r * 33 + lane] * sa + sb;
                        v = fminf(fmaxf(v, 0.f), 6.f);
                        C[(size_t)gm * ldc + gn] = v;
                    }
                }
            } else {  // EPI 1: transposed final out; M == 16384
                for (int c = 0; c < 32; c++) {
                    int gn = n0 + c;
                    if (gn >= N) break;
                    int m = m0 + lane;
                    int b = m >> 8, l = m & 255;
                    C[((size_t)(b * D_MODEL + gn)) * L_SEQ + l] = tp[lane * 33 + c];
                    m = m0 + 32 + lane;
                    b = m >> 8; l = m & 255;
                    C[((size_t)(b * D_MODEL + gn)) * L_SEQ + l] = tp[(lane + 32) * 33 + c];
                }
            }
        }
    }
}

// ----------------------------------------------------------------------------
__global__ void prep_bn_kernel(const float* __restrict__ gamma,
                               const float* __restrict__ beta,
                               const float* __restrict__ mean,
                               const float* __restrict__ var) {
    int i = blockIdx.x * 256 + threadIdx.x;
    if (i < 4 * DIM) {
        float iv = rsqrtf(var[i] + 1e-5f) * gamma[i];
        g_bninv[i]  = iv;
        g_bnbias[i] = beta[i] - mean[i] * iv;
    }
}

// ----------------------------------------------------------------------------
__global__ void build_comb_kernel(const float* __restrict__ x,
                                  const float* __restrict__ pc) {
    size_t idx = (size_t)blockIdx.x * 256 + threadIdx.x;
    if (idx >= (size_t)BATCH * COMB * L_SEQ) return;
    int l = (int)(idx % L_SEQ);
    int c = (int)((idx / L_SEQ) % COMB);
    int b = (int)(idx / ((size_t)L_SEQ * COMB));
    float v;
    if (c < IN_IMG) {
        v = x[((size_t)(b * IN_IMG + c)) * L_SEQ + l];
    } else if (c == IN_IMG) {
        int w = l & 15;
        v = -0.3f + 0.6f * (float)w / 15.0f;
    } else if (c == IN_IMG + 1) {
        int h = l >> 4;
        v = -0.3f + 0.6f * (float)h / 15.0f;
    } else {
        v = pc[b * IN_PC + (c - IN_IMG - 2)];
    }
    g_comb[((size_t)(b * COMB + c)) * L_SEQ + l] = v;
    g_seq[((size_t)(b * L_SEQ + l)) * D_MODEL + c] = v;
}

// ----------------------------------------------------------------------------
__global__ void pool_avg_kernel() {
    __shared__ float s[32][257];
    int b  = blockIdx.y;
    int c0 = blockIdx.x * 32;
    int tid = threadIdx.x;
    for (int i = tid; i < 32 * 256; i += 256) {
        int cl = i >> 8, l = i & 255;
        int c = c0 + cl;
        s[cl][l] = (c < COMB) ? g_comb[((size_t)(b * COMB + c)) * L_SEQ + l] : 0.f;
    }
    __syncthreads();
    for (int oidx = tid; oidx < 275 * 32; oidx += 256) {
        int cl = oidx & 31;
        int q  = oidx >> 5;
        int sdim, qb, base;
        if (q < 25)       { sdim = 5;  qb = q;       base = POOL5_OFF;  }
        else if (q < 106) { sdim = 9;  qb = q - 25;  base = POOL9_OFF;  }
        else              { sdim = 13; qb = q - 106; base = POOL13_OFF; }
        int o = qb / sdim, p = qb % sdim;
        int h0 = (o * 16) / sdim, h1 = ((o + 1) * 16 + sdim - 1) / sdim;
        int w0 = (p * 16) / sdim, w1 = ((p + 1) * 16 + sdim - 1) / sdim;
        float sum = 0.f;
        for (int h = h0; h < h1; h++)
            for (int w = w0; w < w1; w++)
                sum += s[cl][h * 16 + w];
        sum *= 1.0f / (float)((h1 - h0) * (w1 - w0));
        int c = c0 + cl;
        if (c < COMB)
            g_pooled[((size_t)(base + b * sdim * sdim + qb)) * COMB + c] = sum;
    }
}

// ----------------------------------------------------------------------------
__global__ void pool0_mean_kernel() {
    int b = blockIdx.x;
    int d = threadIdx.x;
    float s = 0.f;
    for (int l = 0; l < L_SEQ; l++)
        s += g_p0[((size_t)(b * L_SEQ + l)) * DIM + d];
    g_y0[b * DIM + d] = s * (1.0f / (float)L_SEQ);
}

// ----------------------------------------------------------------------------
__global__ void fill_pool_cols_kernel() {
    int m = blockIdx.x;
    int t = threadIdx.x;
    int b = m >> 8, l = m & 255;
    int h = l >> 4, w = l & 15;
    int si = t >> 7, d = t & 127;
    float v;
    if (si == 0) {
        v = g_y0[b * DIM + d];
    } else {
        int sdim = (si == 1) ? 5 : (si == 2) ? 9 : 13;
        int base = (si == 1) ? POOL5_OFF : (si == 2) ? POOL9_OFF : POOL13_OFF;
        float sh = (h + 0.5f) * (float)sdim / 16.0f - 0.5f;
        sh = fminf(fmaxf(sh, 0.f), (float)sdim - 1.f);
        int h0 = (int)sh;
        int h1 = min(h0 + 1, sdim - 1);
        float fh = sh - (float)h0;
        float sw = (w + 0.5f) * (float)sdim / 16.0f - 0.5f;
        sw = fminf(fmaxf(sw, 0.f), (float)sdim - 1.f);
        int w0 = (int)sw;
        int w1 = min(w0 + 1, sdim - 1);
        float fw = sw - (float)w0;
        const float* Y = g_ys + (size_t)(base + b * sdim * sdim) * DIM;
        float v00 = Y[(size_t)(h0 * sdim + w0) * DIM + d];
        float v01 = Y[(size_t)(h0 * sdim + w1) * DIM + d];
        float v10 = Y[(size_t)(h1 * sdim + w0) * DIM + d];
        float v11 = Y[(size_t)(h1 * sdim + w1) * DIM + d];
        v = (1.f - fh) * ((1.f - fw) * v00 + fw * v01)
          +        fh  * ((1.f - fw) * v10 + fw * v11);
    }
    g_seq[(size_t)m * D_MODEL + COMB + t] = v;
}

// ----------------------------------------------------------------------------
// conv1d + SiLU; writes u as bf16 split (coalesced along d), pads zeroed
// ----------------------------------------------------------------------------
__global__ void conv1d_silu_kernel(const float* __restrict__ w,
                                   const float* __restrict__ bias) {
    int d = blockIdx.x * 256 + threadIdx.x;
    int m = blockIdx.y;
    if (d >= WX_K) return;
    __nv_bfloat16 h, lo;
    if (d < D_INNER) {
        int b = m >> 8, l = m & 255;
        float acc = bias[d];
        #pragma unroll
        for (int k = 0; k < D_CONV; k++) {
            int ls = l + k - (D_CONV - 1);
            if (ls >= 0)
                acc += w[d * D_CONV + k] * g_xz[((size_t)(b * L_SEQ + ls)) * (2 * D_INNER) + d];
        }
        float sg = 1.f / (1.f + __expf(-acc));
        split1(acc * sg, h, lo);
    } else {
        h = __float2bfloat16(0.f);
        lo = h;
    }
    g_uah[(size_t)m * WX_K + d] = h;
    g_ual[(size_t)m * WX_K + d] = lo;
}

// ----------------------------------------------------------------------------
// selective scan; u from split; writes y split directly (coalesced along d)
// ----------------------------------------------------------------------------
__global__ __launch_bounds__(256)
void scan_kernel(const float* __restrict__ A_log, const float* __restrict__ Dp) {
    __shared__ float sB[L_SEQ][D_STATE];
    __shared__ float sC[L_SEQ][D_STATE];
    int b = blockIdx.y;
    int d = blockIdx.x * 256 + threadIdx.x;
    int tid = threadIdx.x;
    for (int i = tid; i < L_SEQ * D_STATE; i += 256) {
        int l = i >> 4, n = i & 15;
        const float* row = g_dbl + (size_t)(b * L_SEQ + l) * XPROJ_LD;
        sB[l][n] = row[DT_RANK + n];
        sC[l][n] = row[DT_RANK + D_STATE + n];
    }
    __syncthreads();
    if (d >= D_INNER) {
        if (d < W2_K) {
            __nv_bfloat16 z16 = __float2bfloat16(0.f);
            for (int l = 0; l < L_SEQ; l++) {
                size_t m = (size_t)(b * L_SEQ + l);
                g_yh[m * W2_K + d] = z16;
                g_yl[m * W2_K + d] = z16;
            }
        }
        return;
    }

    float Ad[D_STATE];
    #pragma unroll
    for (int n = 0; n < D_STATE; n++) Ad[n] = -expf(A_log[d * D_STATE + n]);
    float Dd = Dp[d];
    float hst[D_STATE];
    #pragma unroll
    for (int n = 0; n < D_STATE; n++) hst[n] = 0.f;

    for (int l = 0; l < L_SEQ; l++) {
        size_t m = (size_t)(b * L_SEQ + l);
        float dt = g_dt[m * D_INNER + d];
        float u  = __bfloat162float(g_uah[m * WX_K + d])
                 + __bfloat162float(g_ual[m * WX_K + d]);
        float z  = g_xz[m * (2 * D_INNER) + D_INNER + d];
        float dtu = dt * u;
        float y = 0.f;
        #pragma unroll
        for (int n = 0; n < D_STATE; n++) {
            float dA = __expf(dt * Ad[n]);
            hst[n] = dA * hst[n] + dtu * sB[l][n];
            y = fmaf(hst[n], sC[l][n], y);
        }
        float sig = 1.f / (1.f + __expf(-z));
        float v = (y + u * Dd) * (z * sig);
        __nv_bfloat16 hh, ll;
        split1(v, hh, ll);
        g_yh[m * W2_K + d] = hh;
        g_yl[m * W2_K + d] = ll;
    }
}

// ----------------------------------------------------------------------------
extern "C" void kernel_launch(void* const* d_in, const int* in_sizes, int n_in,
                              void* d_out, int out_size) {
    const float* x          = (const float*)d_in[0];
    const float* pc_emb     = (const float*)d_in[1];
    const float* conv_w     = (const float*)d_in[2];
    const float* bn_gamma   = (const float*)d_in[3];
    const float* bn_beta    = (const float*)d_in[4];
    const float* bn_mean    = (const float*)d_in[5];
    const float* bn_var     = (const float*)d_in[6];
    const float* in_proj_w  = (const float*)d_in[7];
    const float* conv1d_w   = (const float*)d_in[8];
    const float* conv1d_b   = (const float*)d_in[9];
    const float* x_proj_w   = (const float*)d_in[10];
    const float* dt_proj_w  = (const float*)d_in[11];
    const float* dt_proj_b  = (const float*)d_in[12];
    const float* A_log      = (const float*)d_in[13];
    const float* Dp         = (const float*)d_in[14];
    const float* out_proj_w = (const float*)d_in[15];
    float* out = (float*)d_out;

    float *p_seq, *p_xz, *p_dbl, *p_dt, *p_p0, *p_pooled, *p_ys, *p_bninv, *p_bnbias;
    __nv_bfloat16 *p_w1h, *p_w1l, *p_w2h, *p_w2l, *p_wxh, *p_wxl, *p_wdh, *p_wdl, *p_wch, *p_wcl;
    __nv_bfloat16 *p_ah, *p_al, *p_uah, *p_ual, *p_dah, *p_dal, *p_yh, *p_yl;
    cudaGetSymbolAddress((void**)&p_seq,    g_seq);
    cudaGetSymbolAddress((void**)&p_xz,     g_xz);
    cudaGetSymbolAddress((void**)&p_dbl,    g_dbl);
    cudaGetSymbolAddress((void**)&p_dt,     g_dt);
    cudaGetSymbolAddress((void**)&p_p0,     g_p0);
    cudaGetSymbolAddress((void**)&p_pooled, g_pooled);
    cudaGetSymbolAddress((void**)&p_ys,     g_ys);
    cudaGetSymbolAddress((void**)&p_bninv,  g_bninv);
    cudaGetSymbolAddress((void**)&p_bnbias, g_bnbias);
    cudaGetSymbolAddress((void**)&p_w1h, g_w1h);  cudaGetSymbolAddress((void**)&p_w1l, g_w1l);
    cudaGetSymbolAddress((void**)&p_w2h, g_w2h);  cudaGetSymbolAddress((void**)&p_w2l, g_w2l);
    cudaGetSymbolAddress((void**)&p_wxh, g_wxh);  cudaGetSymbolAddress((void**)&p_wxl, g_wxl);
    cudaGetSymbolAddress((void**)&p_wdh, g_wdh);  cudaGetSymbolAddress((void**)&p_wdl, g_wdl);
    cudaGetSymbolAddress((void**)&p_wch, g_wch);  cudaGetSymbolAddress((void**)&p_wcl, g_wcl);
    cudaGetSymbolAddress((void**)&p_ah,  g_ah);   cudaGetSymbolAddress((void**)&p_al,  g_al);
    cudaGetSymbolAddress((void**)&p_uah, g_uah);  cudaGetSymbolAddress((void**)&p_ual, g_ual);
    cudaGetSymbolAddress((void**)&p_dah, g_dah);  cudaGetSymbolAddress((void**)&p_dal, g_dal);
    cudaGetSymbolAddress((void**)&p_yh,  g_yh);   cudaGetSymbolAddress((void**)&p_yl,  g_yl);

    // 1) BN fold + weight pre-splits
    prep_bn_kernel<<<2, 256>>>(bn_gamma, bn_beta, bn_mean, bn_var);
    {
        size_t n;
        n = (size_t)WC_ROWS * WC_K;
        split_kernel<<<(unsigned)((n + 255) / 256), 256>>>(conv_w, COMB, 512, COMB, p_wch, p_wcl, WC_ROWS, WC_K);
        n = (size_t)W1_ROWS * W1_K;
        split_kernel<<<(unsigned)((n + 255) / 256), 256>>>(in_proj_w, D_MODEL, 2 * D_INNER, D_MODEL, p_w1h, p_w1l, W1_ROWS, W1_K);
        n = (size_t)WX_ROWS * WX_K;
        split_kernel<<<(unsigned)((n + 255) / 256), 256>>>(x_proj_w, D_INNER, XPROJ_N, D_INNER, p_wxh, p_wxl, WX_ROWS, WX_K);
        n = (size_t)WD_ROWS * WD_K;
        split_kernel<<<(unsigned)((n + 255) / 256), 256>>>(dt_proj_w, DT_RANK, D_INNER, DT_RANK, p_wdh, p_wdl, WD_ROWS, WD_K);
        n = (size_t)W2_ROWS * W2_K;
        split_kernel<<<(unsigned)((n + 255) / 256), 256>>>(out_proj_w, D_INNER, D_MODEL, D_INNER, p_w2h, p_w2l, W2_ROWS, W2_K);
    }

    // 2) build comb
    {
        size_t total = (size_t)BATCH * COMB * L_SEQ;
        build_comb_kernel<<<(unsigned)((total + 255) / 256), 256>>>(x, pc_emb);
    }

    // 3) adaptive pools
    pool_avg_kernel<<<dim3(25, BATCH), 256>>>();

    // 4) conv0 full-res (fp32-A path)
    mma_gemm_kernel<4, false><<<dim3(1, M_TOTAL / 128), 256>>>(
        p_seq, nullptr, D_MODEL, p_wch, p_wcl, WC_K, p_p0, DIM,
        M_TOTAL, DIM, COMB, WC_K, p_bninv, p_bnbias);

    // 5) pool0 mean
    pool0_mean_kernel<<<BATCH, DIM>>>();

    // 6) pooled-branch convs (fp32-A path)
    {
        const int sM[3]   = {1600, 5184, 10816};
        const int sOff[3] = {POOL5_OFF, POOL9_OFF, POOL13_OFF};
        for (int i = 0; i < 3; i++) {
            int pool = i + 1;
            mma_gemm_kernel<4, false><<<dim3(1, (sM[i] + 127) / 128), 256>>>(
                p_pooled + (size_t)sOff[i] * COMB, nullptr, COMB,
                p_wch + (size_t)pool * DIM * WC_K, p_wcl + (size_t)pool * DIM * WC_K, WC_K,
                p_ys + (size_t)sOff[i] * DIM, DIM,
                sM[i], DIM, COMB, WC_K,
                p_bninv + pool * DIM, p_bnbias + pool * DIM);
        }
    }

    // 7) fill pool cols, split seq -> bf16 hi/lo
    fill_pool_cols_kernel<<<M_TOTAL, 512>>>();
    {
        size_t n = (size_t)M_TOTAL * W1_K;
        split_kernel<<<(unsigned)((n + 255) / 256), 256>>>(
            p_seq, D_MODEL, M_TOTAL, D_MODEL, p_ah, p_al, M_TOTAL, W1_K);
    }

    // 8) in_proj (pre-split A) -> g_xz
    mma_gemm_kernel<0, true><<<dim3(W1_ROWS / 128, M_TOTAL / 128), 256>>>(
        p_ah, p_al, W1_K, p_w1h, p_w1l, W1_K, p_xz, 2 * D_INNER,
        M_TOTAL, 2 * D_INNER, D_MODEL, W1_K, nullptr, nullptr);

    // 9) conv1d + SiLU (writes u split directly)
    conv1d_silu_kernel<<<dim3((WX_K + 255) / 256, M_TOTAL), 256>>>(conv1d_w, conv1d_b);

    // 10) x_proj (pre-split A) -> g_dbl
    mma_gemm_kernel<0, true><<<dim3(1, M_TOTAL / 128), 256>>>(
        p_uah, p_ual, WX_K, p_wxh, p_wxl, WX_K, p_dbl, XPROJ_LD,
        M_TOTAL, XPROJ_N, D_INNER, WX_K, nullptr, nullptr);

    // 10b) split dtA (cols 0..80 of g_dbl)
    {
        size_t n = (size_t)M_TOTAL * WD_K;
        split_kernel<<<(unsigned)((n + 255) / 256), 256>>>(
            p_dbl, XPROJ_LD, M_TOTAL, DT_RANK, p_dah, p_dal, M_TOTAL, WD_K);
    }

    // 11) dt_proj (pre-split A, softplus) -> g_dt
    mma_gemm_kernel<3, true><<<dim3(WD_ROWS / 128, M_TOTAL / 128), 256>>>(
        p_dah, p_dal, WD_K, p_wdh, p_wdl, WD_K, p_dt, D_INNER,
        M_TOTAL, D_INNER, DT_RANK, WD_K, nullptr, dt_proj_b);

    // 12) selective scan (writes y split directly)
    scan_kernel<<<dim3((W2_K + 255) / 256, BATCH), 256>>>(A_log, Dp);

    // 13) out_proj (pre-split A, fused transpose) -> out
    mma_gemm_kernel<1, true><<<dim3(W2_ROWS / 128, M_TOTAL / 128), 256>>>(
        p_yh, p_yl, W2_K, p_w2h, p_w2l, W2_K, out, 0,
        M_TOTAL, D_MODEL, D_INNER, W2_K, nullptr, nullptr);
}

// round 17
// speedup vs baseline: 1.2632x; 1.0538x over previous
#include <cuda_runtime.h>
#include <cuda_bf16.h>
#include <cstdint>

// ----------------------------------------------------------------------------
// Problem constants
// ----------------------------------------------------------------------------
#define BATCH     64
#define L_SEQ     256
#define IN_IMG    512
#define IN_PC     256
#define COMB      770
#define DIM       128
#define D_MODEL   1282
#define D_INNER   2564
#define D_STATE   16
#define D_CONV    4
#define DT_RANK   81
#define XPROJ_N   113
#define XPROJ_LD  116
#define M_TOTAL   (BATCH * L_SEQ)      // 16384

#define POOL5_OFF   0
#define POOL9_OFF   1600
#define POOL13_OFF  6784
#define POOL_ROWS   17600

// padded weight dims (rows mult 128, K mult 32)
#define W1_ROWS  5248
#define W1_K     1312
#define W2_ROWS  1408
#define W2_K     2592
#define WX_ROWS  128
#define WX_K     2592
#define WD_ROWS  2688
#define WD_K     96
#define WC_ROWS  512
#define WC_K     800

// merged-split region prefix sums (elements)
#define SP_WC   ((size_t)WC_ROWS * WC_K)
#define SP_P1   SP_WC
#define SP_P2   (SP_P1 + (size_t)W1_ROWS * W1_K)
#define SP_P3   (SP_P2 + (size_t)WX_ROWS * WX_K)
#define SP_P4   (SP_P3 + (size_t)WD_ROWS * WD_K)
#define SP_TOT  (SP_P4 + (size_t)W2_ROWS * W2_K)

// merged conv-GEMM grid.y boundaries
#define CG_Y0   128
#define CG_Y1   141
#define CG_Y2   182
#define CG_Y3   267

// ----------------------------------------------------------------------------
// Device scratch (static)
// ----------------------------------------------------------------------------
__device__ __align__(16) float g_seq   [(size_t)M_TOTAL * D_MODEL];
__device__ __align__(16) float g_comb  [(size_t)BATCH * COMB * L_SEQ];
__device__ __align__(16) float g_xz    [(size_t)M_TOTAL * 2 * D_INNER];
__device__ __align__(16) float g_dbl   [(size_t)M_TOTAL * XPROJ_LD];
__device__ __align__(16) float g_dt    [(size_t)M_TOTAL * D_INNER];
__device__ __align__(16) float g_p0    [(size_t)M_TOTAL * DIM];
__device__ __align__(16) float g_y0    [BATCH * DIM];
__device__ __align__(16) float g_pooled[(size_t)POOL_ROWS * COMB];
__device__ __align__(16) float g_ys    [(size_t)POOL_ROWS * DIM];
__device__ __align__(16) float g_bninv [4 * DIM];
__device__ __align__(16) float g_bnbias[4 * DIM];

// pre-split bf16 weights (hi/lo), zero-padded rows & K
__device__ __align__(256) __nv_bfloat16 g_w1h[(size_t)W1_ROWS * W1_K];
__device__ __align__(256) __nv_bfloat16 g_w1l[(size_t)W1_ROWS * W1_K];
__device__ __align__(256) __nv_bfloat16 g_w2h[(size_t)W2_ROWS * W2_K];
__device__ __align__(256) __nv_bfloat16 g_w2l[(size_t)W2_ROWS * W2_K];
__device__ __align__(256) __nv_bfloat16 g_wxh[(size_t)WX_ROWS * WX_K];
__device__ __align__(256) __nv_bfloat16 g_wxl[(size_t)WX_ROWS * WX_K];
__device__ __align__(256) __nv_bfloat16 g_wdh[(size_t)WD_ROWS * WD_K];
__device__ __align__(256) __nv_bfloat16 g_wdl[(size_t)WD_ROWS * WD_K];
__device__ __align__(256) __nv_bfloat16 g_wch[(size_t)WC_ROWS * WC_K];
__device__ __align__(256) __nv_bfloat16 g_wcl[(size_t)WC_ROWS * WC_K];

// pre-split bf16 activations
__device__ __align__(256) __nv_bfloat16 g_ah [(size_t)M_TOTAL * W1_K];
__device__ __align__(256) __nv_bfloat16 g_al [(size_t)M_TOTAL * W1_K];
__device__ __align__(256) __nv_bfloat16 g_uah[(size_t)M_TOTAL * WX_K];
__device__ __align__(256) __nv_bfloat16 g_ual[(size_t)M_TOTAL * WX_K];
__device__ __align__(256) __nv_bfloat16 g_dah[(size_t)M_TOTAL * WD_K];
__device__ __align__(256) __nv_bfloat16 g_dal[(size_t)M_TOTAL * WD_K];
__device__ __align__(256) __nv_bfloat16 g_yh [(size_t)M_TOTAL * W2_K];
__device__ __align__(256) __nv_bfloat16 g_yl [(size_t)M_TOTAL * W2_K];

// ----------------------------------------------------------------------------
// PTX helpers
// ----------------------------------------------------------------------------
__device__ __forceinline__ uint32_t smem_to_u32(const void* p) {
    uint32_t a;
    asm("{ .reg .u64 t; cvta.to.shared.u64 t, %1; cvt.u32.u64 %0, t; }"
        : "=r"(a) : "l"(p));
    return a;
}
__device__ __forceinline__ void ldsm4(uint32_t* f, uint32_t addr) {
    asm volatile("ldmatrix.sync.aligned.m8n8.x4.shared.b16 {%0,%1,%2,%3}, [%4];"
                 : "=r"(f[0]), "=r"(f[1]), "=r"(f[2]), "=r"(f[3]) : "r"(addr));
}
__device__ __forceinline__ void mma16816(float* d, const uint32_t* a,
                                         uint32_t b0, uint32_t b1) {
    asm volatile(
        "mma.sync.aligned.m16n8k16.row.col.f32.bf16.bf16.f32 "
        "{%0,%1,%2,%3}, {%4,%5,%6,%7}, {%8,%9}, {%0,%1,%2,%3};"
        : "+f"(d[0]), "+f"(d[1]), "+f"(d[2]), "+f"(d[3])
        : "r"(a[0]), "r"(a[1]), "r"(a[2]), "r"(a[3]), "r"(b0), "r"(b1));
}
__device__ __forceinline__ void split1(float v, __nv_bfloat16& h, __nv_bfloat16& l) {
    h = __float2bfloat16(v);
    l = __float2bfloat16(v - __bfloat162float(h));
}
__device__ __forceinline__ void cvt_hilo(const float* v, uint4& hi, uint4& lo) {
    uint32_t h[4], l[4];
    #pragma unroll
    for (int i = 0; i < 4; i++) {
        __nv_bfloat16 h0, l0, h1, l1;
        split1(v[2*i], h0, l0);
        split1(v[2*i+1], h1, l1);
        h[i] = (uint32_t)__bfloat16_as_ushort(h0) | ((uint32_t)__bfloat16_as_ushort(h1) << 16);
        l[i] = (uint32_t)__bfloat16_as_ushort(l0) | ((uint32_t)__bfloat16_as_ushort(l1) << 16);
    }
    hi = make_uint4(h[0], h[1], h[2], h[3]);
    lo = make_uint4(l[0], l[1], l[2], l[3]);
}
__device__ __forceinline__ void load_unit(const float* p, bool rowok, int krem,
                                          bool al8, float* v) {
    if (rowok && al8 && krem >= 8) {
        const float2* q = (const float2*)p;
        float2 a = q[0], b = q[1], c = q[2], d = q[3];
        v[0] = a.x; v[1] = a.y; v[2] = b.x; v[3] = b.y;
        v[4] = c.x; v[5] = c.y; v[6] = d.x; v[7] = d.y;
    } else {
        #pragma unroll
        for (int i = 0; i < 8; i++)
            v[i] = (rowok && i < krem) ? p[i] : 0.f;
    }
}

// ----------------------------------------------------------------------------
// fp32 -> bf16 hi/lo split with zero padding (seq / dtA activations)
// ----------------------------------------------------------------------------
__global__ void split_kernel(const float* __restrict__ src, int srcld,
                             int R, int K,
                             __nv_bfloat16* __restrict__ hi,
                             __nv_bfloat16* __restrict__ lo,
                             int Rpad, int Kpad) {
    size_t idx = (size_t)blockIdx.x * 256 + threadIdx.x;
    if (idx >= (size_t)Rpad * Kpad) return;
    int k = (int)(idx % Kpad);
    int r = (int)(idx / Kpad);
    float v = (r < R && k < K) ? src[(size_t)r * srcld + k] : 0.f;
    __nv_bfloat16 h, l;
    split1(v, h, l);
    hi[idx] = h;
    lo[idx] = l;
}

// ----------------------------------------------------------------------------
// merged weight split: all five weight tensors in one launch
// ----------------------------------------------------------------------------
__device__ __forceinline__ void split_region(const float* src, int srcld,
                                             int R, int K, int Kpad,
                                             __nv_bfloat16* hi, __nv_bfloat16* lo,
                                             size_t local) {
    int k = (int)(local % Kpad);
    int r = (int)(local / Kpad);
    float v = (r < R && k < K) ? src[(size_t)r * srcld + k] : 0.f;
    __nv_bfloat16 h, l;
    split1(v, h, l);
    hi[local] = h;
    lo[local] = l;
}

__global__ void split_all_kernel(const float* __restrict__ conv_w,
                                 const float* __restrict__ in_proj_w,
                                 const float* __restrict__ x_proj_w,
                                 const float* __restrict__ dt_proj_w,
                                 const float* __restrict__ out_proj_w) {
    size_t idx = (size_t)blockIdx.x * 256 + threadIdx.x;
    if (idx >= SP_TOT) return;
    if (idx < SP_P1) {
        split_region(conv_w, COMB, 512, COMB, WC_K, g_wch, g_wcl, idx);
    } else if (idx < SP_P2) {
        split_region(in_proj_w, D_MODEL, 2 * D_INNER, D_MODEL, W1_K, g_w1h, g_w1l, idx - SP_P1);
    } else if (idx < SP_P3) {
        split_region(x_proj_w, D_INNER, XPROJ_N, D_INNER, WX_K, g_wxh, g_wxl, idx - SP_P2);
    } else if (idx < SP_P4) {
        split_region(dt_proj_w, DT_RANK, D_INNER, DT_RANK, WD_K, g_wdh, g_wdl, idx - SP_P3);
    } else {
        split_region(out_proj_w, D_INNER, D_MODEL, D_INNER, W2_K, g_w2h, g_w2l, idx - SP_P4);
    }
}

// ----------------------------------------------------------------------------
// HMMA bf16x3-split GEMM body (R15-proven inner structure).
//   ASP=false: A fp32, in-register split    ASP=true: A pre-split bf16 hi/lo
// B always pre-split bf16 hi/lo, padded.
// CTA 128x128, 8 warps (2m x 4n), warp 64x32, K-chunk 32, single-stage smem.
// EPI 0: plain fp32   EPI 1: transposed (b,c,l)   EPI 3: softplus   EPI 4: BN+ReLU6
// ----------------------------------------------------------------------------
#define SOFF_AH 0
#define SOFF_AL 8192
#define SOFF_BH 16384
#define SOFF_BL 24576

template <int EPI, bool ASP>
__device__ __forceinline__
void gemm_body(unsigned char* smem_buf,
               const void* Aah, const void* Aal, int lda,
               const __nv_bfloat16* Bh, const __nv_bfloat16* Bl, int ldb,
               float* C, int ldc,
               int M, int N, int K, int Kp,
               const float* ea, const float* eb,
               int bm, int bn) {
    const uint32_t sbase = smem_to_u32(smem_buf);
    const int tid = threadIdx.x;
    const int lane = tid & 31, wid = tid >> 5;
    const int wm = wid >> 2, wn = wid & 3;
    const int nchunks = Kp / 32;
    const bool alA = ((lda & 1) == 0);

    float acc[4][4][4];
    #pragma unroll
    for (int i = 0; i < 4; i++)
        #pragma unroll
        for (int j = 0; j < 4; j++)
            #pragma unroll
            for (int q = 0; q < 4; q++) acc[i][j][q] = 0.f;

    const int lrow = lane & 15;
    const int lkh  = lane >> 4;

    for (int ch = 0; ch < nchunks; ch++) {
        const int k0 = ch * 32;
        #pragma unroll
        for (int uu = 0; uu < 2; uu++) {
            int u = tid + uu * 256;
            int r = u >> 2, cu = u & 3;
            uint32_t soff = (uint32_t)(r * 64 + ((cu ^ ((r >> 1) & 3)) << 4));
            int gk = k0 + cu * 8;
            if (ASP) {
                size_t goa = (size_t)(bm + r) * lda + gk;
                *(uint4*)(smem_buf + SOFF_AH + soff) =
                    *(const uint4*)((const __nv_bfloat16*)Aah + goa);
                *(uint4*)(smem_buf + SOFF_AL + soff) =
                    *(const uint4*)((const __nv_bfloat16*)Aal + goa);
            } else {
                float va[8];
                load_unit((const float*)Aah + (size_t)(bm + r) * lda + gk,
                          (bm + r) < M, K - gk, alA, va);
                uint4 hi, lo;
                cvt_hilo(va, hi, lo);
                *(uint4*)(smem_buf + SOFF_AH + soff) = hi;
                *(uint4*)(smem_buf + SOFF_AL + soff) = lo;
            }
            size_t gob = (size_t)(bn + r) * ldb + gk;
            *(uint4*)(smem_buf + SOFF_BH + soff) = *(const uint4*)(Bh + gob);
            *(uint4*)(smem_buf + SOFF_BL + soff) = *(const uint4*)(Bl + gob);
        }
        __syncthreads();
        #pragma unroll
        for (int k16 = 0; k16 < 2; k16++) {
            const int cbase = k16 * 2 + lkh;
            uint32_t ahf[4][4], alf[4][4], bhf[4][2], blf[4][2];
            #pragma unroll
            for (int mi = 0; mi < 4; mi++) {
                int r = wm * 64 + mi * 16 + lrow;
                uint32_t off = (uint32_t)(r * 64 + ((cbase ^ ((r >> 1) & 3)) << 4));
                ldsm4(ahf[mi], sbase + SOFF_AH + off);
                ldsm4(alf[mi], sbase + SOFF_AL + off);
            }
            #pragma unroll
            for (int ni = 0; ni < 2; ni++) {
                int r = wn * 32 + ni * 16 + lrow;
                uint32_t off = (uint32_t)(r * 64 + ((cbase ^ ((r >> 1) & 3)) << 4));
                uint32_t bt[4];
                ldsm4(bt, sbase + SOFF_BH + off);
                bhf[ni * 2 + 0][0] = bt[0]; bhf[ni * 2 + 0][1] = bt[2];
                bhf[ni * 2 + 1][0] = bt[1]; bhf[ni * 2 + 1][1] = bt[3];
                ldsm4(bt, sbase + SOFF_BL + off);
                blf[ni * 2 + 0][0] = bt[0]; blf[ni * 2 + 0][1] = bt[2];
                blf[ni * 2 + 1][0] = bt[1]; blf[ni * 2 + 1][1] = bt[3];
            }
            #pragma unroll
            for (int mi = 0; mi < 4; mi++)
                #pragma unroll
                for (int nj = 0; nj < 4; nj++) {
                    mma16816(acc[mi][nj], ahf[mi], bhf[nj][0], bhf[nj][1]);
                    mma16816(acc[mi][nj], ahf[mi], blf[nj][0], blf[nj][1]);
                    mma16816(acc[mi][nj], alf[mi], bhf[nj][0], bhf[nj][1]);
                }
        }
        __syncthreads();
    }

    // ---- epilogue ----
    const int m0 = bm + wm * 64, n0 = bn + wn * 32;
    const int tr = lane >> 2, tc2 = (lane & 3) * 2;
    #pragma unroll
    for (int pass = 0; pass < 2; pass++) {
        __syncthreads();
        if (wm == pass) {
            float* tp = (float*)(smem_buf + (size_t)wn * 8448);
            #pragma unroll
            for (int mi = 0; mi < 4; mi++)
                #pragma unroll
                for (int nj = 0; nj < 4; nj++) {
                    int r0 = mi * 16 + tr, c0 = nj * 8 + tc2;
                    tp[r0 * 33 + c0]           = acc[mi][nj][0];
                    tp[r0 * 33 + c0 + 1]       = acc[mi][nj][1];
                    tp[(r0 + 8) * 33 + c0]     = acc[mi][nj][2];
                    tp[(r0 + 8) * 33 + c0 + 1] = acc[mi][nj][3];
                }
            __syncwarp();
            if (EPI == 0) {
                int gn = n0 + lane;
                if (gn < N)
                    for (int r = 0; r < 64; r++) {
                        int gm = m0 + r;
                        if (gm < M) C[(size_t)gm * ldc + gn] = tp[r * 33 + lane];
                    }
            } else if (EPI == 3) {
                int gn = n0 + lane;
                if (gn < N) {
                    float bias = eb[gn];
                    for (int r = 0; r < 64; r++) {
                        int gm = m0 + r;
                        if (gm >= M) break;
                        float v = tp[r * 33 + lane] + bias;
                        v = (v > 20.f) ? v : log1pf(expf(v));
                        C[(size_t)gm * ldc + gn] = v;
                    }
                }
            } else if (EPI == 4) {
                int gn = n0 + lane;
                if (gn < N) {
                    float sa = ea[gn], sb = eb[gn];
                    for (int r = 0; r < 64; r++) {
                        int gm = m0 + r;
                        if (gm >= M) break;
                        float v = tp[r * 33 + lane] * sa + sb;
                        v = fminf(fmaxf(v, 0.f), 6.f);
                        C[(size_t)gm * ldc + gn] = v;
                    }
                }
            } else {  // EPI 1: transposed final out; M == 16384
                for (int c = 0; c < 32; c++) {
                    int gn = n0 + c;
                    if (gn >= N) break;
                    int m = m0 + lane;
                    int b = m >> 8, l = m & 255;
                    C[((size_t)(b * D_MODEL + gn)) * L_SEQ + l] = tp[lane * 33 + c];
                    m = m0 + 32 + lane;
                    b = m >> 8; l = m & 255;
                    C[((size_t)(b * D_MODEL + gn)) * L_SEQ + l] = tp[(lane + 32) * 33 + c];
                }
            }
        }
    }
}

// generic GEMM kernel (in_proj / x_proj / dt_proj / out_proj)
template <int EPI, bool ASP>
__global__ __launch_bounds__(256)
void mma_gemm_kernel(const void* __restrict__ Aah, const void* __restrict__ Aal,
                     int lda,
                     const __nv_bfloat16* __restrict__ Bh,
                     const __nv_bfloat16* __restrict__ Bl, int ldb,
                     float* __restrict__ C, int ldc,
                     int M, int N, int K, int Kp,
                     const float* __restrict__ ea, const float* __restrict__ eb) {
    __shared__ __align__(16) unsigned char smem_buf[34048];
    gemm_body<EPI, ASP>(smem_buf, Aah, Aal, lda, Bh, Bl, ldb, C, ldc,
                        M, N, K, Kp, ea, eb, blockIdx.y * 128, blockIdx.x * 128);
}

// merged conv-branch GEMM: conv0 + 3 pooled branches in one launch (grid.y=267)
__global__ __launch_bounds__(256)
void conv_gemm_all_kernel(const float* __restrict__ seq,
                          const float* __restrict__ pooled,
                          const __nv_bfloat16* __restrict__ wch,
                          const __nv_bfloat16* __restrict__ wcl,
                          float* __restrict__ p0,
                          float* __restrict__ ys,
                          const float* __restrict__ bninv,
                          const float* __restrict__ bnbias) {
    __shared__ __align__(16) unsigned char smem_buf[34048];
    int y = blockIdx.y;
    const float* A;
    float* C;
    int lda, M, bm, pool;
    if (y < CG_Y0) {
        A = seq; lda = D_MODEL; M = M_TOTAL; bm = y * 128; pool = 0; C = p0;
    } else if (y < CG_Y1) {
        A = pooled + (size_t)POOL5_OFF * COMB; lda = COMB; M = 1600;
        bm = (y - CG_Y0) * 128; pool = 1; C = ys + (size_t)POOL5_OFF * DIM;
    } else if (y < CG_Y2) {
        A = pooled + (size_t)POOL9_OFF * COMB; lda = COMB; M = 5184;
        bm = (y - CG_Y1) * 128; pool = 2; C = ys + (size_t)POOL9_OFF * DIM;
    } else {
        A = pooled + (size_t)POOL13_OFF * COMB; lda = COMB; M = 10816;
        bm = (y - CG_Y2) * 128; pool = 3; C = ys + (size_t)POOL13_OFF * DIM;
    }
    gemm_body<4, false>(smem_buf, A, nullptr, lda,
                        wch + (size_t)pool * DIM * WC_K,
                        wcl + (size_t)pool * DIM * WC_K, WC_K,
                        C, DIM, M, DIM, COMB, WC_K,
                        bninv + pool * DIM, bnbias + pool * DIM, bm, 0);
}

// ----------------------------------------------------------------------------
__global__ void prep_bn_kernel(const float* __restrict__ gamma,
                               const float* __restrict__ beta,
                               const float* __restrict__ mean,
                               const float* __restrict__ var) {
    int i = blockIdx.x * 256 + threadIdx.x;
    if (i < 4 * DIM) {
        float iv = rsqrtf(var[i] + 1e-5f) * gamma[i];
        g_bninv[i]  = iv;
        g_bnbias[i] = beta[i] - mean[i] * iv;
    }
}

// ----------------------------------------------------------------------------
__global__ void build_comb_kernel(const float* __restrict__ x,
                                  const float* __restrict__ pc) {
    size_t idx = (size_t)blockIdx.x * 256 + threadIdx.x;
    if (idx >= (size_t)BATCH * COMB * L_SEQ) return;
    int l = (int)(idx % L_SEQ);
    int c = (int)((idx / L_SEQ) % COMB);
    int b = (int)(idx / ((size_t)L_SEQ * COMB));
    float v;
    if (c < IN_IMG) {
        v = x[((size_t)(b * IN_IMG + c)) * L_SEQ + l];
    } else if (c == IN_IMG) {
        int w = l & 15;
        v = -0.3f + 0.6f * (float)w / 15.0f;
    } else if (c == IN_IMG + 1) {
        int h = l >> 4;
        v = -0.3f + 0.6f * (float)h / 15.0f;
    } else {
        v = pc[b * IN_PC + (c - IN_IMG - 2)];
    }
    g_comb[((size_t)(b * COMB + c)) * L_SEQ + l] = v;
    g_seq[((size_t)(b * L_SEQ + l)) * D_MODEL + c] = v;
}

// ----------------------------------------------------------------------------
__global__ void pool_avg_kernel() {
    __shared__ float s[32][257];
    int b  = blockIdx.y;
    int c0 = blockIdx.x * 32;
    int tid = threadIdx.x;
    for (int i = tid; i < 32 * 256; i += 256) {
        int cl = i >> 8, l = i & 255;
        int c = c0 + cl;
        s[cl][l] = (c < COMB) ? g_comb[((size_t)(b * COMB + c)) * L_SEQ + l] : 0.f;
    }
    __syncthreads();
    for (int oidx = tid; oidx < 275 * 32; oidx += 256) {
        int cl = oidx & 31;
        int q  = oidx >> 5;
        int sdim, qb, base;
        if (q < 25)       { sdim = 5;  qb = q;       base = POOL5_OFF;  }
        else if (q < 106) { sdim = 9;  qb = q - 25;  base = POOL9_OFF;  }
        else              { sdim = 13; qb = q - 106; base = POOL13_OFF; }
        int o = qb / sdim, p = qb % sdim;
        int h0 = (o * 16) / sdim, h1 = ((o + 1) * 16 + sdim - 1) / sdim;
        int w0 = (p * 16) / sdim, w1 = ((p + 1) * 16 + sdim - 1) / sdim;
        float sum = 0.f;
        for (int h = h0; h < h1; h++)
            for (int w = w0; w < w1; w++)
                sum += s[cl][h * 16 + w];
        sum *= 1.0f / (float)((h1 - h0) * (w1 - w0));
        int c = c0 + cl;
        if (c < COMB)
            g_pooled[((size_t)(base + b * sdim * sdim + qb)) * COMB + c] = sum;
    }
}

// ----------------------------------------------------------------------------
__global__ void pool0_mean_kernel() {
    int b = blockIdx.x;
    int d = threadIdx.x;
    float s = 0.f;
    for (int l = 0; l < L_SEQ; l++)
        s += g_p0[((size_t)(b * L_SEQ + l)) * DIM + d];
    g_y0[b * DIM + d] = s * (1.0f / (float)L_SEQ);
}

// ----------------------------------------------------------------------------
__global__ void fill_pool_cols_kernel() {
    int m = blockIdx.x;
    int t = threadIdx.x;
    int b = m >> 8, l = m & 255;
    int h = l >> 4, w = l & 15;
    int si = t >> 7, d = t & 127;
    float v;
    if (si == 0) {
        v = g_y0[b * DIM + d];
    } else {
        int sdim = (si == 1) ? 5 : (si == 2) ? 9 : 13;
        int base = (si == 1) ? POOL5_OFF : (si == 2) ? POOL9_OFF : POOL13_OFF;
        float sh = (h + 0.5f) * (float)sdim / 16.0f - 0.5f;
        sh = fminf(fmaxf(sh, 0.f), (float)sdim - 1.f);
        int h0 = (int)sh;
        int h1 = min(h0 + 1, sdim - 1);
        float fh = sh - (float)h0;
        float sw = (w + 0.5f) * (float)sdim / 16.0f - 0.5f;
        sw = fminf(fmaxf(sw, 0.f), (float)sdim - 1.f);
        int w0 = (int)sw;
        int w1 = min(w0 + 1, sdim - 1);
        float fw = sw - (float)w0;
        const float* Y = g_ys + (size_t)(base + b * sdim * sdim) * DIM;
        float v00 = Y[(size_t)(h0 * sdim + w0) * DIM + d];
        float v01 = Y[(size_t)(h0 * sdim + w1) * DIM + d];
        float v10 = Y[(size_t)(h1 * sdim + w0) * DIM + d];
        float v11 = Y[(size_t)(h1 * sdim + w1) * DIM + d];
        v = (1.f - fh) * ((1.f - fw) * v00 + fw * v01)
          +        fh  * ((1.f - fw) * v10 + fw * v11);
    }
    g_seq[(size_t)m * D_MODEL + COMB + t] = v;
}

// ----------------------------------------------------------------------------
// conv1d + SiLU; writes u as bf16 split (coalesced along d), pads zeroed
// ----------------------------------------------------------------------------
__global__ void conv1d_silu_kernel(const float* __restrict__ w,
                                   const float* __restrict__ bias) {
    int d = blockIdx.x * 256 + threadIdx.x;
    int m = blockIdx.y;
    if (d >= WX_K) return;
    __nv_bfloat16 h, lo;
    if (d < D_INNER) {
        int b = m >> 8, l = m & 255;
        float acc = bias[d];
        #pragma unroll
        for (int k = 0; k < D_CONV; k++) {
            int ls = l + k - (D_CONV - 1);
            if (ls >= 0)
                acc += w[d * D_CONV + k] * g_xz[((size_t)(b * L_SEQ + ls)) * (2 * D_INNER) + d];
        }
        float sg = 1.f / (1.f + __expf(-acc));
        split1(acc * sg, h, lo);
    } else {
        h = __float2bfloat16(0.f);
        lo = h;
    }
    g_uah[(size_t)m * WX_K + d] = h;
    g_ual[(size_t)m * WX_K + d] = lo;
}

// ----------------------------------------------------------------------------
// selective scan; u from split; writes y split directly (coalesced along d)
// ----------------------------------------------------------------------------
__global__ __launch_bounds__(256)
void scan_kernel(const float* __restrict__ A_log, const float* __restrict__ Dp) {
    __shared__ float sB[L_SEQ][D_STATE];
    __shared__ float sC[L_SEQ][D_STATE];
    int b = blockIdx.y;
    int d = blockIdx.x * 256 + threadIdx.x;
    int tid = threadIdx.x;
    for (int i = tid; i < L_SEQ * D_STATE; i += 256) {
        int l = i >> 4, n = i & 15;
        const float* row = g_dbl + (size_t)(b * L_SEQ + l) * XPROJ_LD;
        sB[l][n] = row[DT_RANK + n];
        sC[l][n] = row[DT_RANK + D_STATE + n];
    }
    __syncthreads();
    if (d >= D_INNER) {
        if (d < W2_K) {
            __nv_bfloat16 z16 = __float2bfloat16(0.f);
            for (int l = 0; l < L_SEQ; l++) {
                size_t m = (size_t)(b * L_SEQ + l);
                g_yh[m * W2_K + d] = z16;
                g_yl[m * W2_K + d] = z16;
            }
        }
        return;
    }

    float Ad[D_STATE];
    #pragma unroll
    for (int n = 0; n < D_STATE; n++) Ad[n] = -expf(A_log[d * D_STATE + n]);
    float Dd = Dp[d];
    float hst[D_STATE];
    #pragma unroll
    for (int n = 0; n < D_STATE; n++) hst[n] = 0.f;

    for (int l = 0; l < L_SEQ; l++) {
        size_t m = (size_t)(b * L_SEQ + l);
        float dt = g_dt[m * D_INNER + d];
        float u  = __bfloat162float(g_uah[m * WX_K + d])
                 + __bfloat162float(g_ual[m * WX_K + d]);
        float z  = g_xz[m * (2 * D_INNER) + D_INNER + d];
        float dtu = dt * u;
        float y = 0.f;
        #pragma unroll
        for (int n = 0; n < D_STATE; n++) {
            float dA = __expf(dt * Ad[n]);
            hst[n] = dA * hst[n] + dtu * sB[l][n];
            y = fmaf(hst[n], sC[l][n], y);
        }
        float sig = 1.f / (1.f + __expf(-z));
        float v = (y + u * Dd) * (z * sig);
        __nv_bfloat16 hh, ll;
        split1(v, hh, ll);
        g_yh[m * W2_K + d] = hh;
        g_yl[m * W2_K + d] = ll;
    }
}

// ----------------------------------------------------------------------------
extern "C" void kernel_launch(void* const* d_in, const int* in_sizes, int n_in,
                              void* d_out, int out_size) {
    const float* x          = (const float*)d_in[0];
    const float* pc_emb     = (const float*)d_in[1];
    const float* conv_w     = (const float*)d_in[2];
    const float* bn_gamma   = (const float*)d_in[3];
    const float* bn_beta    = (const float*)d_in[4];
    const float* bn_mean    = (const float*)d_in[5];
    const float* bn_var     = (const float*)d_in[6];
    const float* in_proj_w  = (const float*)d_in[7];
    const float* conv1d_w   = (const float*)d_in[8];
    const float* conv1d_b   = (const float*)d_in[9];
    const float* x_proj_w   = (const float*)d_in[10];
    const float* dt_proj_w  = (const float*)d_in[11];
    const float* dt_proj_b  = (const float*)d_in[12];
    const float* A_log      = (const float*)d_in[13];
    const float* Dp         = (const float*)d_in[14];
    const float* out_proj_w = (const float*)d_in[15];
    float* out = (float*)d_out;

    float *p_seq, *p_xz, *p_dbl, *p_dt, *p_p0, *p_pooled, *p_ys, *p_bninv, *p_bnbias;
    __nv_bfloat16 *p_w1h, *p_w1l, *p_w2h, *p_w2l, *p_wxh, *p_wxl, *p_wdh, *p_wdl, *p_wch, *p_wcl;
    __nv_bfloat16 *p_ah, *p_al, *p_uah, *p_ual, *p_dah, *p_dal, *p_yh, *p_yl;
    cudaGetSymbolAddress((void**)&p_seq,    g_seq);
    cudaGetSymbolAddress((void**)&p_xz,     g_xz);
    cudaGetSymbolAddress((void**)&p_dbl,    g_dbl);
    cudaGetSymbolAddress((void**)&p_dt,     g_dt);
    cudaGetSymbolAddress((void**)&p_p0,     g_p0);
    cudaGetSymbolAddress((void**)&p_pooled, g_pooled);
    cudaGetSymbolAddress((void**)&p_ys,     g_ys);
    cudaGetSymbolAddress((void**)&p_bninv,  g_bninv);
    cudaGetSymbolAddress((void**)&p_bnbias, g_bnbias);
    cudaGetSymbolAddress((void**)&p_w1h, g_w1h);  cudaGetSymbolAddress((void**)&p_w1l, g_w1l);
    cudaGetSymbolAddress((void**)&p_w2h, g_w2h);  cudaGetSymbolAddress((void**)&p_w2l, g_w2l);
    cudaGetSymbolAddress((void**)&p_wxh, g_wxh);  cudaGetSymbolAddress((void**)&p_wxl, g_wxl);
    cudaGetSymbolAddress((void**)&p_wdh, g_wdh);  cudaGetSymbolAddress((void**)&p_wdl, g_wdl);
    cudaGetSymbolAddress((void**)&p_wch, g_wch);  cudaGetSymbolAddress((void**)&p_wcl, g_wcl);
    cudaGetSymbolAddress((void**)&p_ah,  g_ah);   cudaGetSymbolAddress((void**)&p_al,  g_al);
    cudaGetSymbolAddress((void**)&p_uah, g_uah);  cudaGetSymbolAddress((void**)&p_ual, g_ual);
    cudaGetSymbolAddress((void**)&p_dah, g_dah);  cudaGetSymbolAddress((void**)&p_dal, g_dal);
    cudaGetSymbolAddress((void**)&p_yh,  g_yh);   cudaGetSymbolAddress((void**)&p_yl,  g_yl);

    // 1) BN fold + merged weight pre-split
    prep_bn_kernel<<<2, 256>>>(bn_gamma, bn_beta, bn_mean, bn_var);
    split_all_kernel<<<(unsigned)((SP_TOT + 255) / 256), 256>>>(
        conv_w, in_proj_w, x_proj_w, dt_proj_w, out_proj_w);

    // 2) build comb
    {
        size_t total = (size_t)BATCH * COMB * L_SEQ;
        build_comb_kernel<<<(unsigned)((total + 255) / 256), 256>>>(x, pc_emb);
    }

    // 3) adaptive pools
    pool_avg_kernel<<<dim3(25, BATCH), 256>>>();

    // 4) ALL conv branches in one launch (conv0 + pool5/9/13)
    conv_gemm_all_kernel<<<dim3(1, CG_Y3), 256>>>(
        p_seq, p_pooled, p_wch, p_wcl, p_p0, p_ys, p_bninv, p_bnbias);

    // 5) pool0 mean
    pool0_mean_kernel<<<BATCH, DIM>>>();

    // 6) fill pool cols, split seq -> bf16 hi/lo
    fill_pool_cols_kernel<<<M_TOTAL, 512>>>();
    {
        size_t n = (size_t)M_TOTAL * W1_K;
        split_kernel<<<(unsigned)((n + 255) / 256), 256>>>(
            p_seq, D_MODEL, M_TOTAL, D_MODEL, p_ah, p_al, M_TOTAL, W1_K);
    }

    // 7) in_proj (pre-split A) -> g_xz
    mma_gemm_kernel<0, true><<<dim3(W1_ROWS / 128, M_TOTAL / 128), 256>>>(
        p_ah, p_al, W1_K, p_w1h, p_w1l, W1_K, p_xz, 2 * D_INNER,
        M_TOTAL, 2 * D_INNER, D_MODEL, W1_K, nullptr, nullptr);

    // 8) conv1d + SiLU (writes u split directly)
    conv1d_silu_kernel<<<dim3((WX_K + 255) / 256, M_TOTAL), 256>>>(conv1d_w, conv1d_b);

    // 9) x_proj (pre-split A) -> g_dbl
    mma_gemm_kernel<0, true><<<dim3(1, M_TOTAL / 128), 256>>>(
        p_uah, p_ual, WX_K, p_wxh, p_wxl, WX_K, p_dbl, XPROJ_LD,
        M_TOTAL, XPROJ_N, D_INNER, WX_K, nullptr, nullptr);

    // 9b) split dtA (cols 0..80 of g_dbl)
    {
        size_t n = (size_t)M_TOTAL * WD_K;
        split_kernel<<<(unsigned)((n + 255) / 256), 256>>>(
            p_dbl, XPROJ_LD, M_TOTAL, DT_RANK, p_dah, p_dal, M_TOTAL, WD_K);
    }

    // 10) dt_proj (pre-split A, softplus) -> g_dt
    mma_gemm_kernel<3, true><<<dim3(WD_ROWS / 128, M_TOTAL / 128), 256>>>(
        p_dah, p_dal, WD_K, p_wdh, p_wdl, WD_K, p_dt, D_INNER,
        M_TOTAL, D_INNER, DT_RANK, WD_K, nullptr, dt_proj_b);

    // 11) selective scan (writes y split directly)
    scan_kernel<<<dim3((W2_K + 255) / 256, BATCH), 256>>>(A_log, Dp);

    // 12) out_proj (pre-split A, fused transpose) -> out
    mma_gemm_kernel<1, true><<<dim3(W2_ROWS / 128, M_TOTAL / 128), 256>>>(
        p_yh, p_yl, W2_K, p_w2h, p_w2l, W2_K, out, 0,
        M_TOTAL, D_MODEL, D_INNER, W2_K, nullptr, nullptr);
}